// round 2
// baseline (speedup 1.0000x reference)
#include <cuda_runtime.h>
#include <cstdint>

#define BS 4
#define NQ 16384
#define EMB 128
#define NH 8
#define NP 4
#define HD 16
#define BEV 128
#define M_TOTAL (BS * NQ)   // 65536

// Scratch (device globals: allocation-guard safe)
__device__ float g_value[M_TOTAL * EMB];     // value projection, layout (b, q, h*16+d)
__device__ float g_sampled[M_TOTAL * EMB];   // sampled features,  layout (b, q, h*16+d)

// ---------------------------------------------------------------------------
// GEMM: C[M x 128] = A[M x 128] @ W[128 x 128] + bias (+ 2*resid)
// Block: 256 threads, tile 128 rows x 128 cols, K chunked by 32.
// Thread (tx,ty) in 16x16 computes strided 8x8: rows ty+16j, cols tx+16i.
// ---------------------------------------------------------------------------
__global__ __launch_bounds__(256) void gemm128_kernel(
    const float* __restrict__ A, const float* __restrict__ W,
    const float* __restrict__ bias, const float* __restrict__ resid,
    float* __restrict__ C)
{
    __shared__ float As[128][33];   // +1 pad: conflict-free As[row][k] reads
    __shared__ float Ws[32][128];

    const int t  = threadIdx.x;
    const int tx = t & 15;
    const int ty = t >> 4;
    const int rowBase = blockIdx.x * 128;

    float acc[8][8];
#pragma unroll
    for (int j = 0; j < 8; j++)
#pragma unroll
        for (int i = 0; i < 8; i++) acc[j][i] = 0.0f;

    for (int kc = 0; kc < 128; kc += 32) {
        // Load A chunk: 128 rows x 32 cols (coalesced 128B per 32-lane group)
        {
            const int col = t & 31;
            const int r0  = t >> 5;
#pragma unroll
            for (int r = 0; r < 16; r++) {
                const int row = r0 + r * 8;
                As[row][col] = A[(size_t)(rowBase + row) * EMB + kc + col];
            }
        }
        // Load W chunk: 32 rows x 128 cols
        {
#pragma unroll
            for (int r = 0; r < 16; r++) {
                const int idx = t + r * 256;
                const int row = idx >> 7;
                const int col = idx & 127;
                Ws[row][col] = W[(size_t)(kc + row) * EMB + col];
            }
        }
        __syncthreads();

#pragma unroll
        for (int k = 0; k < 32; k++) {
            float a[8], w[8];
#pragma unroll
            for (int j = 0; j < 8; j++) a[j] = As[ty + 16 * j][k];
#pragma unroll
            for (int i = 0; i < 8; i++) w[i] = Ws[k][tx + 16 * i];
#pragma unroll
            for (int j = 0; j < 8; j++)
#pragma unroll
                for (int i = 0; i < 8; i++)
                    acc[j][i] = fmaf(a[j], w[i], acc[j][i]);
        }
        __syncthreads();
    }

#pragma unroll
    for (int j = 0; j < 8; j++) {
        const int row = rowBase + ty + 16 * j;
#pragma unroll
        for (int i = 0; i < 8; i++) {
            const int col = tx + 16 * i;
            float v = acc[j][i] + bias[col];
            if (resid) v += 2.0f * resid[(size_t)row * EMB + col];
            C[(size_t)row * EMB + col] = v;
        }
    }
}

// ---------------------------------------------------------------------------
// Sampler: per thread = (query, head).
//  - projects 8 offsets + 4 attn logits from the 128-dim query row
//  - softmax over 4 points
//  - bilinear gather from g_value (zero padding outside), weighted sum
// Block: 256 threads -> 32 queries. Dynamic smem: combined weights + q tile.
// ---------------------------------------------------------------------------
__global__ __launch_bounds__(256) void msda_sample_kernel(
    const float* __restrict__ query,
    const float* __restrict__ W_off,  const float* __restrict__ b_off,
    const float* __restrict__ W_attn, const float* __restrict__ b_attn)
{
    extern __shared__ float sm[];
    float* Wc = sm;                    // [128][96]: 0..63 = W_off row, 64..95 = W_attn row
    float* qs = sm + 128 * 96;         // [32][129] padded

    const int t  = threadIdx.x;
    const int m0 = blockIdx.x * 32;

    // Stage combined weights
    for (int i = t; i < 128 * 96; i += 256) {
        const int k = i / 96, c = i % 96;
        Wc[i] = (c < 64) ? W_off[k * 64 + c] : W_attn[k * 32 + (c - 64)];
    }
    // Stage query tile
    for (int i = t; i < 32 * 128; i += 256) {
        const int ql = i >> 7, k = i & 127;
        qs[ql * 129 + k] = query[(size_t)(m0 + ql) * EMB + k];
    }
    __syncthreads();

    const int h  = t & 7;
    const int ql = t >> 3;
    const int m  = m0 + ql;           // global row in (b, q) flat space
    const int b  = m / NQ;
    const int q  = m - b * NQ;

    // 12 projections for this head
    float off[8], lg[4];
#pragma unroll
    for (int o = 0; o < 8; o++) off[o] = b_off[h * 8 + o];
#pragma unroll
    for (int a = 0; a < 4; a++) lg[a] = b_attn[h * 4 + a];

    const float* qrow = qs + ql * 129;
#pragma unroll 4
    for (int k = 0; k < 128; k++) {
        const float qk = qrow[k];
        const float4 w0 = *(const float4*)(Wc + k * 96 + h * 8);
        const float4 w1 = *(const float4*)(Wc + k * 96 + h * 8 + 4);
        const float4 wa = *(const float4*)(Wc + k * 96 + 64 + h * 4);
        off[0] = fmaf(qk, w0.x, off[0]); off[1] = fmaf(qk, w0.y, off[1]);
        off[2] = fmaf(qk, w0.z, off[2]); off[3] = fmaf(qk, w0.w, off[3]);
        off[4] = fmaf(qk, w1.x, off[4]); off[5] = fmaf(qk, w1.y, off[5]);
        off[6] = fmaf(qk, w1.z, off[6]); off[7] = fmaf(qk, w1.w, off[7]);
        lg[0]  = fmaf(qk, wa.x, lg[0]);  lg[1]  = fmaf(qk, wa.y, lg[1]);
        lg[2]  = fmaf(qk, wa.z, lg[2]);  lg[3]  = fmaf(qk, wa.w, lg[3]);
    }

    // softmax over points
    float mx = fmaxf(fmaxf(lg[0], lg[1]), fmaxf(lg[2], lg[3]));
    float aw[4];
    float s = 0.0f;
#pragma unroll
    for (int p = 0; p < 4; p++) { aw[p] = __expf(lg[p] - mx); s += aw[p]; }
    const float inv = 1.0f / s;
#pragma unroll
    for (int p = 0; p < 4; p++) aw[p] *= inv;

    // bilinear sampling from g_value
    const float* vb = g_value + (size_t)b * NQ * EMB + h * HD;
    float4 acc0 = make_float4(0.f, 0.f, 0.f, 0.f);
    float4 acc1 = make_float4(0.f, 0.f, 0.f, 0.f);
    float4 acc2 = make_float4(0.f, 0.f, 0.f, 0.f);
    float4 acc3 = make_float4(0.f, 0.f, 0.f, 0.f);

    const float scale = 128.0f / 127.0f;
    const float refx = (float)(q & 127) * scale;
    const float refy = (float)(q >> 7) * scale;

#pragma unroll
    for (int p = 0; p < 4; p++) {
        const float px = refx + off[p * 2 + 0] - 0.5f;
        const float py = refy + off[p * 2 + 1] - 0.5f;
        const float x0f = floorf(px), y0f = floorf(py);
        const int x0 = (int)x0f, y0 = (int)y0f;
        const float wx = px - x0f, wy = py - y0f;
        const float w = aw[p];
        const float w00 = w * (1.f - wx) * (1.f - wy);
        const float w01 = w * wx * (1.f - wy);
        const float w10 = w * (1.f - wx) * wy;
        const float w11 = w * wx * wy;

        const int xs[4] = {x0, x0 + 1, x0, x0 + 1};
        const int ys[4] = {y0, y0, y0 + 1, y0 + 1};
        const float ws[4] = {w00, w01, w10, w11};
#pragma unroll
        for (int c = 0; c < 4; c++) {
            const int xi = xs[c], yi = ys[c];
            if (xi >= 0 && xi < BEV && yi >= 0 && yi < BEV) {
                const float4* cp = (const float4*)(vb + (size_t)(yi * BEV + xi) * EMB);
                const float cw = ws[c];
                float4 c0 = cp[0], c1 = cp[1], c2 = cp[2], c3 = cp[3];
                acc0.x = fmaf(cw, c0.x, acc0.x); acc0.y = fmaf(cw, c0.y, acc0.y);
                acc0.z = fmaf(cw, c0.z, acc0.z); acc0.w = fmaf(cw, c0.w, acc0.w);
                acc1.x = fmaf(cw, c1.x, acc1.x); acc1.y = fmaf(cw, c1.y, acc1.y);
                acc1.z = fmaf(cw, c1.z, acc1.z); acc1.w = fmaf(cw, c1.w, acc1.w);
                acc2.x = fmaf(cw, c2.x, acc2.x); acc2.y = fmaf(cw, c2.y, acc2.y);
                acc2.z = fmaf(cw, c2.z, acc2.z); acc2.w = fmaf(cw, c2.w, acc2.w);
                acc3.x = fmaf(cw, c3.x, acc3.x); acc3.y = fmaf(cw, c3.y, acc3.y);
                acc3.z = fmaf(cw, c3.z, acc3.z); acc3.w = fmaf(cw, c3.w, acc3.w);
            }
        }
    }

    float4* outp = (float4*)(g_sampled + (size_t)m * EMB + h * HD);
    outp[0] = acc0; outp[1] = acc1; outp[2] = acc2; outp[3] = acc3;
}

// ---------------------------------------------------------------------------

extern "C" void kernel_launch(void* const* d_in, const int* in_sizes, int n_in,
                              void* d_out, int out_size)
{
    const float* query  = (const float*)d_in[0];
    const float* W_off  = (const float*)d_in[1];
    const float* b_off  = (const float*)d_in[2];
    const float* W_attn = (const float*)d_in[3];
    const float* b_attn = (const float*)d_in[4];
    const float* W_val  = (const float*)d_in[5];
    const float* b_val  = (const float*)d_in[6];
    const float* W_out  = (const float*)d_in[7];
    const float* b_out  = (const float*)d_in[8];
    float* out = (float*)d_out;

    float* gv = nullptr;
    float* gs = nullptr;
    cudaGetSymbolAddress((void**)&gv, g_value);
    cudaGetSymbolAddress((void**)&gs, g_sampled);

    const int smem_bytes = (128 * 96 + 32 * 129) * (int)sizeof(float);
    cudaFuncSetAttribute(msda_sample_kernel,
                         cudaFuncAttributeMaxDynamicSharedMemorySize, smem_bytes);

    // 1) value projection
    gemm128_kernel<<<M_TOTAL / 128, 256>>>(query, W_val, b_val, nullptr, gv);

    // 2) offsets/attn projection + softmax + bilinear sampling
    msda_sample_kernel<<<M_TOTAL / 32, 256, smem_bytes>>>(query, W_off, b_off,
                                                          W_attn, b_attn);

    // 3) output projection + bias + 2*query residual
    gemm128_kernel<<<M_TOTAL / 128, 256>>>(gs, W_out, b_out, query, out);
}

// round 3
// speedup vs baseline: 3.9408x; 3.9408x over previous
#include <cuda_runtime.h>
#include <cuda_bf16.h>
#include <cstdint>

#define BS 4
#define NQ 16384
#define EMB 128
#define NH 8
#define NP 4
#define HD 16
#define BEV 128
#define M_TOTAL (BS * NQ)   // 65536

// Scratch (device globals: allocation-guard safe)
__device__ float g_value[M_TOTAL * EMB];     // value projection (b, q, h*16+d)
__device__ float g_offattn[M_TOTAL * 96];    // per (b,q): 64 offsets + 32 attn logits
__device__ float g_sampled[M_TOTAL * EMB];   // sampled features
__device__ float g_Wcat[128 * 96];           // [W_off | W_attn] packed
__device__ float g_bcat[96];

// ---------------------------------------------------------------------------
// helpers
// ---------------------------------------------------------------------------
__device__ __forceinline__ uint32_t smem_u32(const void* p) {
    return (uint32_t)__cvta_generic_to_shared(p);
}
__device__ __forceinline__ void ldsm_x4(uint32_t& r0, uint32_t& r1, uint32_t& r2,
                                        uint32_t& r3, uint32_t addr) {
    asm volatile("ldmatrix.sync.aligned.m8n8.x4.shared.b16 {%0,%1,%2,%3},[%4];\n"
                 : "=r"(r0), "=r"(r1), "=r"(r2), "=r"(r3) : "r"(addr));
}
__device__ __forceinline__ void ldsm_x4t(uint32_t& r0, uint32_t& r1, uint32_t& r2,
                                         uint32_t& r3, uint32_t addr) {
    asm volatile("ldmatrix.sync.aligned.m8n8.x4.trans.shared.b16 {%0,%1,%2,%3},[%4];\n"
                 : "=r"(r0), "=r"(r1), "=r"(r2), "=r"(r3) : "r"(addr));
}
__device__ __forceinline__ void mma_bf16(float* d, const uint32_t* a,
                                         const uint32_t* b) {
    asm volatile(
        "mma.sync.aligned.m16n8k16.row.col.f32.bf16.bf16.f32 "
        "{%0,%1,%2,%3},{%4,%5,%6,%7},{%8,%9},{%0,%1,%2,%3};\n"
        : "+f"(d[0]), "+f"(d[1]), "+f"(d[2]), "+f"(d[3])
        : "r"(a[0]), "r"(a[1]), "r"(a[2]), "r"(a[3]), "r"(b[0]), "r"(b[1]));
}

// ---------------------------------------------------------------------------
// bf16 tensor-core GEMM: C[M x N] = A[M x 128] @ W[128 x N] + bias (+2*resid)
// A, W fp32 in global, converted to bf16 in smem; fp32 accumulate.
// Block: 256 threads (8 warps, 4m x 2n), CTA tile 128 x N, K=128 in one stage.
// ---------------------------------------------------------------------------
template <int N, int RESID>
__global__ __launch_bounds__(256) void mma_gemm(
    const float* __restrict__ A, const float* __restrict__ W,
    const float* __restrict__ bias, const float* __restrict__ resid,
    float* __restrict__ C)
{
    constexpr int AST = 136;       // A smem row stride in bf16 elems
    constexpr int WST = N + 8;     // W smem row stride
    constexpr int WN = N / 2;      // per-warp N tile (64 or 48)
    constexpr int NF = WN / 8;     // n-frags per warp (8 or 6)

    extern __shared__ __nv_bfloat16 sm[];
    __nv_bfloat16* As = sm;                  // [128][AST]
    __nv_bfloat16* Ws = sm + 128 * AST;      // [128 k][WST]

    const int t = threadIdx.x;
    const int rowBase = blockIdx.x * 128;

    // --- load A tile 128x128 fp32, convert to bf16 ---
#pragma unroll
    for (int j = 0; j < 16; j++) {
        const int idx = t + j * 256;          // 4096 float4 total
        const int row = idx >> 5;
        const int c4  = idx & 31;
        float4 v = *(const float4*)(A + (size_t)(rowBase + row) * EMB + c4 * 4);
        *(__nv_bfloat162*)(As + row * AST + c4 * 4)     = __floats2bfloat162_rn(v.x, v.y);
        *(__nv_bfloat162*)(As + row * AST + c4 * 4 + 2) = __floats2bfloat162_rn(v.z, v.w);
    }
    // --- load W tile 128xN fp32, convert ---
    constexpr int WF4 = 128 * (N / 4);
    for (int idx = t; idx < WF4; idx += 256) {
        const int row = idx / (N / 4);
        const int cg  = idx % (N / 4);
        float4 v = *(const float4*)(W + (size_t)row * N + cg * 4);
        *(__nv_bfloat162*)(Ws + row * WST + cg * 4)     = __floats2bfloat162_rn(v.x, v.y);
        *(__nv_bfloat162*)(Ws + row * WST + cg * 4 + 2) = __floats2bfloat162_rn(v.z, v.w);
    }
    __syncthreads();

    const int wid = t >> 5, lane = t & 31;
    const int wm = wid & 3, wn = wid >> 2;
    const int m0 = wm * 32;
    const int n0 = wn * WN;

    float acc[2][NF][4];
#pragma unroll
    for (int mf = 0; mf < 2; mf++)
#pragma unroll
        for (int nf = 0; nf < NF; nf++)
#pragma unroll
            for (int i = 0; i < 4; i++) acc[mf][nf][i] = 0.0f;

    // ldmatrix base addresses (bytes)
    const uint32_t asb = smem_u32(As);
    const uint32_t wsb = smem_u32(Ws);
    uint32_t aAddr[2];
#pragma unroll
    for (int mf = 0; mf < 2; mf++)
        aAddr[mf] = asb + ((m0 + mf * 16 + (lane & 15)) * AST + (lane >> 4) * 8) * 2;
    const int kOff = ((lane >> 3) & 1) * 8 + (lane & 7);
    const int cOff = ((lane >> 4) & 1) * 8;
    uint32_t bAddr[NF / 2];
#pragma unroll
    for (int np = 0; np < NF / 2; np++)
        bAddr[np] = wsb + (kOff * WST + n0 + np * 16 + cOff) * 2;

#pragma unroll
    for (int kk = 0; kk < 8; kk++) {
        uint32_t a[2][4];
        ldsm_x4(a[0][0], a[0][1], a[0][2], a[0][3], aAddr[0] + kk * 32);
        ldsm_x4(a[1][0], a[1][1], a[1][2], a[1][3], aAddr[1] + kk * 32);
        uint32_t b[NF][2];
#pragma unroll
        for (int np = 0; np < NF / 2; np++)
            ldsm_x4t(b[2 * np][0], b[2 * np][1], b[2 * np + 1][0], b[2 * np + 1][1],
                     bAddr[np] + kk * 16 * WST * 2);
#pragma unroll
        for (int mf = 0; mf < 2; mf++)
#pragma unroll
            for (int nf = 0; nf < NF; nf++)
                mma_bf16(acc[mf][nf], a[mf], b[nf]);
    }

    // --- epilogue ---
    const int lr = lane >> 2;
    const int lc = (lane & 3) * 2;
#pragma unroll
    for (int mf = 0; mf < 2; mf++)
#pragma unroll
        for (int nf = 0; nf < NF; nf++) {
            const int row = rowBase + m0 + mf * 16 + lr;
            const int col = n0 + nf * 8 + lc;
            const float2 bb = *(const float2*)(bias + col);
            float2 v0 = make_float2(acc[mf][nf][0] + bb.x, acc[mf][nf][1] + bb.y);
            float2 v1 = make_float2(acc[mf][nf][2] + bb.x, acc[mf][nf][3] + bb.y);
            if (RESID) {
                float2 r0 = *(const float2*)(resid + (size_t)row * EMB + col);
                float2 r1 = *(const float2*)(resid + (size_t)(row + 8) * EMB + col);
                v0.x += 2.0f * r0.x; v0.y += 2.0f * r0.y;
                v1.x += 2.0f * r1.x; v1.y += 2.0f * r1.y;
            }
            *(float2*)(C + (size_t)row * N + col) = v0;
            *(float2*)(C + (size_t)(row + 8) * N + col) = v1;
        }
}

// ---------------------------------------------------------------------------
// Pack [W_off | W_attn] into one 128x96 matrix + bias
// ---------------------------------------------------------------------------
__global__ void pack_kernel(const float* __restrict__ Wo, const float* __restrict__ bo,
                            const float* __restrict__ Wa, const float* __restrict__ ba)
{
    const int i = blockIdx.x * 256 + threadIdx.x;
    if (i < 128 * 96) {
        const int k = i / 96, c = i % 96;
        g_Wcat[i] = (c < 64) ? Wo[k * 64 + c] : Wa[k * 32 + (c - 64)];
    }
    if (i < 96) g_bcat[i] = (i < 64) ? bo[i] : ba[i - 64];
}

// ---------------------------------------------------------------------------
// Gather: per thread = (query, head). Reads precomputed offsets/logits,
// softmax over 4 points, 16-corner bilinear gather from g_value.
// ---------------------------------------------------------------------------
__global__ __launch_bounds__(256) void gather_kernel()
{
    const int t = blockIdx.x * 256 + threadIdx.x;   // 524288 threads
    const int h = t & 7;
    const int m = t >> 3;
    const int b = m >> 14;           // m / NQ
    const int q = m & (NQ - 1);

    const float* oa = g_offattn + (size_t)m * 96;
    const float4 o0 = *(const float4*)(oa + h * 8);
    const float4 o1 = *(const float4*)(oa + h * 8 + 4);
    const float4 lv = *(const float4*)(oa + 64 + h * 4);
    const float off[8] = {o0.x, o0.y, o0.z, o0.w, o1.x, o1.y, o1.z, o1.w};
    float lg[4] = {lv.x, lv.y, lv.z, lv.w};

    // softmax over points
    const float mx = fmaxf(fmaxf(lg[0], lg[1]), fmaxf(lg[2], lg[3]));
    float aw[4], s = 0.0f;
#pragma unroll
    for (int p = 0; p < 4; p++) { aw[p] = __expf(lg[p] - mx); s += aw[p]; }
    const float inv = 1.0f / s;
#pragma unroll
    for (int p = 0; p < 4; p++) aw[p] *= inv;

    const float* vb = g_value + (size_t)b * NQ * EMB + h * HD;
    float4 a0 = make_float4(0.f, 0.f, 0.f, 0.f);
    float4 a1 = make_float4(0.f, 0.f, 0.f, 0.f);
    float4 a2 = make_float4(0.f, 0.f, 0.f, 0.f);
    float4 a3 = make_float4(0.f, 0.f, 0.f, 0.f);

    const float scale = 128.0f / 127.0f;
    const float refx = (float)(q & 127) * scale;
    const float refy = (float)(q >> 7) * scale;

#pragma unroll
    for (int p = 0; p < 4; p++) {
        const float px = refx + off[p * 2 + 0] - 0.5f;
        const float py = refy + off[p * 2 + 1] - 0.5f;
        const float x0f = floorf(px), y0f = floorf(py);
        const int x0 = (int)x0f, y0 = (int)y0f;
        const float wx = px - x0f, wy = py - y0f;
        const float w = aw[p];
        const float w00 = w * (1.f - wx) * (1.f - wy);
        const float w01 = w * wx * (1.f - wy);
        const float w10 = w * (1.f - wx) * wy;
        const float w11 = w * wx * wy;

        const int xs[4] = {x0, x0 + 1, x0, x0 + 1};
        const int ys[4] = {y0, y0, y0 + 1, y0 + 1};
        const float ws[4] = {w00, w01, w10, w11};
#pragma unroll
        for (int c = 0; c < 4; c++) {
            const int xi = xs[c], yi = ys[c];
            if (xi >= 0 && xi < BEV && yi >= 0 && yi < BEV) {
                const float4* cp = (const float4*)(vb + (size_t)(yi * BEV + xi) * EMB);
                const float cw = ws[c];
                const float4 c0 = cp[0], c1 = cp[1], c2 = cp[2], c3 = cp[3];
                a0.x = fmaf(cw, c0.x, a0.x); a0.y = fmaf(cw, c0.y, a0.y);
                a0.z = fmaf(cw, c0.z, a0.z); a0.w = fmaf(cw, c0.w, a0.w);
                a1.x = fmaf(cw, c1.x, a1.x); a1.y = fmaf(cw, c1.y, a1.y);
                a1.z = fmaf(cw, c1.z, a1.z); a1.w = fmaf(cw, c1.w, a1.w);
                a2.x = fmaf(cw, c2.x, a2.x); a2.y = fmaf(cw, c2.y, a2.y);
                a2.z = fmaf(cw, c2.z, a2.z); a2.w = fmaf(cw, c2.w, a2.w);
                a3.x = fmaf(cw, c3.x, a3.x); a3.y = fmaf(cw, c3.y, a3.y);
                a3.z = fmaf(cw, c3.z, a3.z); a3.w = fmaf(cw, c3.w, a3.w);
            }
        }
    }

    float4* outp = (float4*)(g_sampled + (size_t)m * EMB + h * HD);
    outp[0] = a0; outp[1] = a1; outp[2] = a2; outp[3] = a3;
}

// ---------------------------------------------------------------------------

extern "C" void kernel_launch(void* const* d_in, const int* in_sizes, int n_in,
                              void* d_out, int out_size)
{
    const float* query  = (const float*)d_in[0];
    const float* W_off  = (const float*)d_in[1];
    const float* b_off  = (const float*)d_in[2];
    const float* W_attn = (const float*)d_in[3];
    const float* b_attn = (const float*)d_in[4];
    const float* W_val  = (const float*)d_in[5];
    const float* b_val  = (const float*)d_in[6];
    const float* W_out  = (const float*)d_in[7];
    const float* b_out  = (const float*)d_in[8];
    float* out = (float*)d_out;

    float *gv = nullptr, *goa = nullptr, *gs = nullptr, *gw = nullptr, *gb = nullptr;
    cudaGetSymbolAddress((void**)&gv,  g_value);
    cudaGetSymbolAddress((void**)&goa, g_offattn);
    cudaGetSymbolAddress((void**)&gs,  g_sampled);
    cudaGetSymbolAddress((void**)&gw,  g_Wcat);
    cudaGetSymbolAddress((void**)&gb,  g_bcat);

    const int smem128 = (128 * 136 + 128 * 136) * 2;   // 69632 B
    const int smem96  = (128 * 136 + 128 * 104) * 2;   // 61440 B
    cudaFuncSetAttribute(mma_gemm<128, 0>, cudaFuncAttributeMaxDynamicSharedMemorySize, smem128);
    cudaFuncSetAttribute(mma_gemm<128, 1>, cudaFuncAttributeMaxDynamicSharedMemorySize, smem128);
    cudaFuncSetAttribute(mma_gemm<96, 0>,  cudaFuncAttributeMaxDynamicSharedMemorySize, smem96);

    // 0) pack combined offset/attn weights
    pack_kernel<<<48, 256>>>(W_off, b_off, W_attn, b_attn);

    // 1) value projection (bf16 tensor cores)
    mma_gemm<128, 0><<<M_TOTAL / 128, 256, smem128>>>(query, W_val, b_val, nullptr, gv);

    // 2) offset/attn projection
    mma_gemm<96, 0><<<M_TOTAL / 128, 256, smem96>>>(query, gw, gb, nullptr, goa);

    // 3) softmax + bilinear gather
    gather_kernel<<<M_TOTAL * NH / 256, 256>>>();

    // 4) output projection + bias + 2*query residual
    mma_gemm<128, 1><<<M_TOTAL / 128, 256, smem128>>>(gs, W_out, b_out, query, out);
}

// round 5
// speedup vs baseline: 5.3918x; 1.3682x over previous
#include <cuda_runtime.h>
#include <cuda_bf16.h>
#include <cstdint>

#define BS 4
#define NQ 16384
#define EMB 128
#define NH 8
#define NP 4
#define HD 16
#define BEV 128
#define M_TOTAL (BS * NQ)   // 65536

// Scratch (device globals: allocation-guard safe)
__device__ float g_value[M_TOTAL * EMB];     // head-major: ((b*8+h)*16384+q)*16+d
__device__ float g_offattn[M_TOTAL * 96];    // ((b*8+h)*16384+q)*12 : 8 off + 4 logits
__device__ float g_sampled[M_TOTAL * EMB];   // head-major like g_value
__device__ float g_Wcat[128 * 96];           // [W_off | W_attn] packed
__device__ float g_bcat[96];

// ---------------------------------------------------------------------------
// helpers
// ---------------------------------------------------------------------------
__device__ __forceinline__ uint32_t smem_u32(const void* p) {
    return (uint32_t)__cvta_generic_to_shared(p);
}
__device__ __forceinline__ void ldsm_x4(uint32_t& r0, uint32_t& r1, uint32_t& r2,
                                        uint32_t& r3, uint32_t addr) {
    asm volatile("ldmatrix.sync.aligned.m8n8.x4.shared.b16 {%0,%1,%2,%3},[%4];\n"
                 : "=r"(r0), "=r"(r1), "=r"(r2), "=r"(r3) : "r"(addr));
}
__device__ __forceinline__ void ldsm_x4t(uint32_t& r0, uint32_t& r1, uint32_t& r2,
                                         uint32_t& r3, uint32_t addr) {
    asm volatile("ldmatrix.sync.aligned.m8n8.x4.trans.shared.b16 {%0,%1,%2,%3},[%4];\n"
                 : "=r"(r0), "=r"(r1), "=r"(r2), "=r"(r3) : "r"(addr));
}
__device__ __forceinline__ void mma_bf16(float* d, const uint32_t* a,
                                         const uint32_t* b) {
    asm volatile(
        "mma.sync.aligned.m16n8k16.row.col.f32.bf16.bf16.f32 "
        "{%0,%1,%2,%3},{%4,%5,%6,%7},{%8,%9},{%0,%1,%2,%3};\n"
        : "+f"(d[0]), "+f"(d[1]), "+f"(d[2]), "+f"(d[3])
        : "r"(a[0]), "r"(a[1]), "r"(a[2]), "r"(a[3]), "r"(b[0]), "r"(b[1]));
}

// ---------------------------------------------------------------------------
// bf16 tensor-core GEMM: C[M x N] = A[M x 128] @ W[128 x N] + bias (+2*resid)
// ALAY: 0 = row-major (m,128);   1 = head-major sampled ((b8+h)*16384+q)*16+d
// CLAY: 0 = row-major;           1 = head-major value;   2 = offattn-12
// ---------------------------------------------------------------------------
template <int N, int ALAY, int CLAY, int RESID>
__global__ __launch_bounds__(256) void mma_gemm(
    const float* __restrict__ A, const float* __restrict__ W,
    const float* __restrict__ bias, const float* __restrict__ resid,
    float* __restrict__ C)
{
    constexpr int AST = 136;       // A smem row stride (bf16)
    constexpr int WST = N + 8;
    constexpr int WN = N / 2;
    constexpr int NF = WN / 8;

    extern __shared__ __nv_bfloat16 sm[];
    __nv_bfloat16* As = sm;                  // [128][AST]
    __nv_bfloat16* Ws = sm + 128 * AST;      // [128][WST]

    const int t = threadIdx.x;
    const int rowBase = blockIdx.x * 128;

    // --- load A tile 128x128 fp32 -> bf16 ---
#pragma unroll
    for (int j = 0; j < 16; j++) {
        const int idx = t + j * 256;
        const int row = idx >> 5;
        const int c4  = idx & 31;
        float4 v;
        if (ALAY == 0) {
            v = *(const float4*)(A + (size_t)(rowBase + row) * EMB + c4 * 4);
        } else {
            const int col = c4 * 4;
            const int h = col >> 4, d = col & 15;
            const int gr = rowBase + row;
            const int b0 = gr >> 14, q0 = gr & 16383;
            v = *(const float4*)(A + ((size_t)(b0 * 8 + h) * NQ + q0) * 16 + d);
        }
        *(__nv_bfloat162*)(As + row * AST + c4 * 4)     = __floats2bfloat162_rn(v.x, v.y);
        *(__nv_bfloat162*)(As + row * AST + c4 * 4 + 2) = __floats2bfloat162_rn(v.z, v.w);
    }
    // --- load W tile 128xN fp32 -> bf16 ---
    constexpr int WF4 = 128 * (N / 4);
    for (int idx = t; idx < WF4; idx += 256) {
        const int row = idx / (N / 4);
        const int cg  = idx % (N / 4);
        float4 v = *(const float4*)(W + (size_t)row * N + cg * 4);
        *(__nv_bfloat162*)(Ws + row * WST + cg * 4)     = __floats2bfloat162_rn(v.x, v.y);
        *(__nv_bfloat162*)(Ws + row * WST + cg * 4 + 2) = __floats2bfloat162_rn(v.z, v.w);
    }
    __syncthreads();

    const int wid = t >> 5, lane = t & 31;
    const int wm = wid & 3, wn = wid >> 2;
    const int m0 = wm * 32;
    const int n0 = wn * WN;

    float acc[2][NF][4];
#pragma unroll
    for (int mf = 0; mf < 2; mf++)
#pragma unroll
        for (int nf = 0; nf < NF; nf++)
#pragma unroll
            for (int i = 0; i < 4; i++) acc[mf][nf][i] = 0.0f;

    const uint32_t asb = smem_u32(As);
    const uint32_t wsb = smem_u32(Ws);
    uint32_t aAddr[2];
#pragma unroll
    for (int mf = 0; mf < 2; mf++)
        aAddr[mf] = asb + ((m0 + mf * 16 + (lane & 15)) * AST + (lane >> 4) * 8) * 2;
    const int kOff = ((lane >> 3) & 1) * 8 + (lane & 7);
    const int cOff = ((lane >> 4) & 1) * 8;
    uint32_t bAddr[NF / 2];
#pragma unroll
    for (int np = 0; np < NF / 2; np++)
        bAddr[np] = wsb + (kOff * WST + n0 + np * 16 + cOff) * 2;

#pragma unroll
    for (int kk = 0; kk < 8; kk++) {
        uint32_t a[2][4];
        ldsm_x4(a[0][0], a[0][1], a[0][2], a[0][3], aAddr[0] + kk * 32);
        ldsm_x4(a[1][0], a[1][1], a[1][2], a[1][3], aAddr[1] + kk * 32);
        uint32_t b[NF][2];
#pragma unroll
        for (int np = 0; np < NF / 2; np++)
            ldsm_x4t(b[2 * np][0], b[2 * np][1], b[2 * np + 1][0], b[2 * np + 1][1],
                     bAddr[np] + kk * 16 * WST * 2);
#pragma unroll
        for (int mf = 0; mf < 2; mf++)
#pragma unroll
            for (int nf = 0; nf < NF; nf++)
                mma_bf16(acc[mf][nf], a[mf], b[nf]);
    }

    // --- epilogue ---
    const int lr = lane >> 2;
    const int lc = (lane & 3) * 2;
#pragma unroll
    for (int mf = 0; mf < 2; mf++)
#pragma unroll
        for (int nf = 0; nf < NF; nf++) {
            const int row = rowBase + m0 + mf * 16 + lr;
            const int col = n0 + nf * 8 + lc;
            const float2 bb = *(const float2*)(bias + col);
            float2 v0 = make_float2(acc[mf][nf][0] + bb.x, acc[mf][nf][1] + bb.y);
            float2 v1 = make_float2(acc[mf][nf][2] + bb.x, acc[mf][nf][3] + bb.y);
            if (CLAY == 0) {
                if (RESID) {
                    float2 r0 = *(const float2*)(resid + (size_t)row * EMB + col);
                    float2 r1 = *(const float2*)(resid + (size_t)(row + 8) * EMB + col);
                    v0.x += 2.0f * r0.x; v0.y += 2.0f * r0.y;
                    v1.x += 2.0f * r1.x; v1.y += 2.0f * r1.y;
                }
                *(float2*)(C + (size_t)row * N + col) = v0;
                *(float2*)(C + (size_t)(row + 8) * N + col) = v1;
            } else if (CLAY == 1) {
                const int h = col >> 4, d = col & 15;
                const int b0 = row >> 14, q0 = row & 16383;
                const size_t base = (size_t)(b0 * 8 + h) * NQ;
                *(float2*)(C + (base + q0) * 16 + d)     = v0;
                *(float2*)(C + (base + q0 + 8) * 16 + d) = v1;
            } else {
                int h, jj;
                if (col < 64) { h = col >> 3; jj = col & 7; }
                else          { h = (col - 64) >> 2; jj = 8 + ((col - 64) & 3); }
                const int b0 = row >> 14, q0 = row & 16383;
                const size_t base = (size_t)(b0 * 8 + h) * NQ;
                *(float2*)(C + (base + q0) * 12 + jj)     = v0;
                *(float2*)(C + (base + q0 + 8) * 12 + jj) = v1;
            }
        }
}

// ---------------------------------------------------------------------------
// Pack [W_off | W_attn] into one 128x96 matrix + bias
// ---------------------------------------------------------------------------
__global__ void pack_kernel(const float* __restrict__ Wo, const float* __restrict__ bo,
                            const float* __restrict__ Wa, const float* __restrict__ ba)
{
    const int i = blockIdx.x * 256 + threadIdx.x;
    if (i < 128 * 96) {
        const int k = i / 96, c = i % 96;
        g_Wcat[i] = (c < 64) ? Wo[k * 64 + c] : Wa[k * 32 + (c - 64)];
    }
    if (i < 96) g_bcat[i] = (i < 64) ? bo[i] : ba[i - 64];
}

// ---------------------------------------------------------------------------
// Tiled gather: block = (b, h, 16x16 query tile). Stages a 24x24 pixel x 16f
// value tile in smem (swizzled for conflict-free LDS.128), then each thread
// does softmax + 16-corner bilinear interpolation. Global fallback for
// corners outside the halo keeps correctness for arbitrary offsets.
// ---------------------------------------------------------------------------
__global__ __launch_bounds__(256) void gather_kernel()
{
    __shared__ float sv[24 * 24 * 16];   // 36,864 B

    const int blk  = blockIdx.x;
    const int tile = blk & 63;
    const int h    = (blk >> 6) & 7;
    const int b    = blk >> 9;
    const int tx0  = (tile & 7) * 16, ty0 = (tile >> 3) * 16;
    const int xlo  = tx0 - 4, ylo = ty0 - 4;
    const int t    = threadIdx.x;

    const float* vsrc = g_value + (size_t)(b * 8 + h) * NQ * 16;

    // --- fill smem tile (swizzled: pixel's float4 #j stored at slot (j+(px>>1))&3) ---
#pragma unroll
    for (int ii = 0; ii < 9; ii++) {
        const int i   = t + ii * 256;            // 0..2303
        const int pix = i >> 2, j = i & 3;
        const int py  = pix / 24, px = pix - py * 24;
        const int gy  = ylo + py, gx = xlo + px;
        float4 v = make_float4(0.f, 0.f, 0.f, 0.f);
        if ((unsigned)gy < 128u && (unsigned)gx < 128u)
            v = *(const float4*)(vsrc + (size_t)(gy * BEV + gx) * 16 + j * 4);
        const int slot = (j + (px >> 1)) & 3;
        *(float4*)(sv + pix * 16 + slot * 4) = v;
    }

    // --- per-thread parameters (coalesced 48B/thread) ---
    const int x = tx0 + (t & 15), y = ty0 + (t >> 4);
    const int q = y * BEV + x;
    const float* oa = g_offattn + ((size_t)(b * 8 + h) * NQ + q) * 12;
    const float4 A0 = *(const float4*)(oa);
    const float4 A1 = *(const float4*)(oa + 4);
    const float4 A2 = *(const float4*)(oa + 8);
    const float off[8] = {A0.x, A0.y, A0.z, A0.w, A1.x, A1.y, A1.z, A1.w};
    float lg[4] = {A2.x, A2.y, A2.z, A2.w};

    __syncthreads();

    // softmax over points
    const float mx = fmaxf(fmaxf(lg[0], lg[1]), fmaxf(lg[2], lg[3]));
    float aw[4], s = 0.0f;
#pragma unroll
    for (int p = 0; p < 4; p++) { aw[p] = __expf(lg[p] - mx); s += aw[p]; }
    const float inv = 1.0f / s;
#pragma unroll
    for (int p = 0; p < 4; p++) aw[p] *= inv;

    const float scale = 128.0f / 127.0f;
    const float refx = (float)x * scale;
    const float refy = (float)y * scale;

    float4 acc[4];
#pragma unroll
    for (int j = 0; j < 4; j++) acc[j] = make_float4(0.f, 0.f, 0.f, 0.f);

#pragma unroll
    for (int p = 0; p < 4; p++) {
        const float px = refx + off[p * 2 + 0] - 0.5f;
        const float py = refy + off[p * 2 + 1] - 0.5f;
        const float x0f = floorf(px), y0f = floorf(py);
        const int x0 = (int)x0f, y0 = (int)y0f;
        const float wx = px - x0f, wy = py - y0f;
        const float w = aw[p];
        const float cws[4] = {w * (1.f - wx) * (1.f - wy), w * wx * (1.f - wy),
                              w * (1.f - wx) * wy,         w * wx * wy};
        const int xs[4] = {x0, x0 + 1, x0, x0 + 1};
        const int ys[4] = {y0, y0, y0 + 1, y0 + 1};
#pragma unroll
        for (int c = 0; c < 4; c++) {
            const int xi = xs[c], yi = ys[c];
            const int sx = xi - xlo, sy = yi - ylo;
            const float cw = cws[c];
            if ((unsigned)sx < 24u && (unsigned)sy < 24u) {
                const float* pp = sv + (sy * 24 + sx) * 16;
                const int ws = (sx >> 1) & 3;
#pragma unroll
                for (int jj = 0; jj < 4; jj++) {
                    const float4 cv = *(const float4*)(pp + (((jj + ws) & 3) << 2));
                    acc[jj].x = fmaf(cw, cv.x, acc[jj].x);
                    acc[jj].y = fmaf(cw, cv.y, acc[jj].y);
                    acc[jj].z = fmaf(cw, cv.z, acc[jj].z);
                    acc[jj].w = fmaf(cw, cv.w, acc[jj].w);
                }
            } else if ((unsigned)xi < 128u && (unsigned)yi < 128u) {
                const float4* cp = (const float4*)(vsrc + (size_t)(yi * BEV + xi) * 16);
#pragma unroll
                for (int jj = 0; jj < 4; jj++) {
                    const float4 cv = cp[jj];
                    acc[jj].x = fmaf(cw, cv.x, acc[jj].x);
                    acc[jj].y = fmaf(cw, cv.y, acc[jj].y);
                    acc[jj].z = fmaf(cw, cv.z, acc[jj].z);
                    acc[jj].w = fmaf(cw, cv.w, acc[jj].w);
                }
            }
        }
    }

    float* outp = g_sampled + ((size_t)(b * 8 + h) * NQ + q) * 16;
#pragma unroll
    for (int jj = 0; jj < 4; jj++) *(float4*)(outp + jj * 4) = acc[jj];
}

// ---------------------------------------------------------------------------

extern "C" void kernel_launch(void* const* d_in, const int* in_sizes, int n_in,
                              void* d_out, int out_size)
{
    const float* query  = (const float*)d_in[0];
    const float* W_off  = (const float*)d_in[1];
    const float* b_off  = (const float*)d_in[2];
    const float* W_attn = (const float*)d_in[3];
    const float* b_attn = (const float*)d_in[4];
    const float* W_val  = (const float*)d_in[5];
    const float* b_val  = (const float*)d_in[6];
    const float* W_out  = (const float*)d_in[7];
    const float* b_out  = (const float*)d_in[8];
    float* out = (float*)d_out;

    float *gv = nullptr, *goa = nullptr, *gs = nullptr, *gw = nullptr, *gb = nullptr;
    cudaGetSymbolAddress((void**)&gv,  g_value);
    cudaGetSymbolAddress((void**)&goa, g_offattn);
    cudaGetSymbolAddress((void**)&gs,  g_sampled);
    cudaGetSymbolAddress((void**)&gw,  g_Wcat);
    cudaGetSymbolAddress((void**)&gb,  g_bcat);

    const int smem128 = (128 * 136 + 128 * 136) * 2;   // 69632 B
    const int smem96  = (128 * 136 + 128 * 104) * 2;   // 61440 B
    cudaFuncSetAttribute(mma_gemm<128, 0, 1, 0>, cudaFuncAttributeMaxDynamicSharedMemorySize, smem128);
    cudaFuncSetAttribute(mma_gemm<96, 0, 2, 0>,  cudaFuncAttributeMaxDynamicSharedMemorySize, smem96);
    cudaFuncSetAttribute(mma_gemm<128, 1, 0, 1>, cudaFuncAttributeMaxDynamicSharedMemorySize, smem128);

    // 0) pack combined offset/attn weights
    pack_kernel<<<48, 256>>>(W_off, b_off, W_attn, b_attn);

    // 1) value projection -> head-major g_value
    mma_gemm<128, 0, 1, 0><<<M_TOTAL / 128, 256, smem128>>>(query, W_val, b_val, nullptr, gv);

    // 2) offset/attn projection -> 12-float per (b,h,q)
    mma_gemm<96, 0, 2, 0><<<M_TOTAL / 128, 256, smem96>>>(query, gw, gb, nullptr, goa);

    // 3) tiled softmax + bilinear gather
    gather_kernel<<<BS * NH * 64, 256>>>();

    // 4) output projection + bias + 2*query residual
    mma_gemm<128, 1, 0, 1><<<M_TOTAL / 128, 256, smem128>>>(gs, W_out, b_out, query, out);
}

// round 8
// speedup vs baseline: 6.3393x; 1.1757x over previous
#include <cuda_runtime.h>
#include <cuda_bf16.h>
#include <cstdint>

#define BS 4
#define NQ 16384
#define EMB 128
#define NH 8
#define NP 4
#define HD 16
#define BEV 128
#define M_TOTAL (BS * NQ)   // 65536

// Scratch (device globals: allocation-guard safe)
__device__ __nv_bfloat16 g_value[M_TOTAL * EMB];    // head-major: ((b*8+h)*NQ+q)*16+d
__device__ float         g_offattn[M_TOTAL * 96];   // ((b*8+h)*NQ+q)*12 : 8 off + 4 logits
__device__ __nv_bfloat16 g_sampled[M_TOTAL * EMB];  // head-major like g_value

// ---------------------------------------------------------------------------
// helpers
// ---------------------------------------------------------------------------
__device__ __forceinline__ uint32_t smem_u32(const void* p) {
    return (uint32_t)__cvta_generic_to_shared(p);
}
__device__ __forceinline__ void ldsm_x4(uint32_t& r0, uint32_t& r1, uint32_t& r2,
                                        uint32_t& r3, uint32_t addr) {
    asm volatile("ldmatrix.sync.aligned.m8n8.x4.shared.b16 {%0,%1,%2,%3},[%4];\n"
                 : "=r"(r0), "=r"(r1), "=r"(r2), "=r"(r3) : "r"(addr));
}
__device__ __forceinline__ void ldsm_x4t(uint32_t& r0, uint32_t& r1, uint32_t& r2,
                                         uint32_t& r3, uint32_t addr) {
    asm volatile("ldmatrix.sync.aligned.m8n8.x4.trans.shared.b16 {%0,%1,%2,%3},[%4];\n"
                 : "=r"(r0), "=r"(r1), "=r"(r2), "=r"(r3) : "r"(addr));
}
__device__ __forceinline__ void mma_bf16(float* d, const uint32_t* a,
                                         const uint32_t* b) {
    asm volatile(
        "mma.sync.aligned.m16n8k16.row.col.f32.bf16.bf16.f32 "
        "{%0,%1,%2,%3},{%4,%5,%6,%7},{%8,%9},{%0,%1,%2,%3};\n"
        : "+f"(d[0]), "+f"(d[1]), "+f"(d[2]), "+f"(d[3])
        : "r"(a[0]), "r"(a[1]), "r"(a[2]), "r"(a[3]), "r"(b[0]), "r"(b[1]));
}

// ---------------------------------------------------------------------------
// bf16 tensor-core GEMM: C[M x N] = A[M x 128] @ W[128 x N] + bias
// AT: 0 = fp32 row-major A;  1 = bf16 head-major A (g_sampled)
// WT: 0 = single fp32 W/bias; 1 = dual source [W1|W2] cols 0..63 | 64..95
// CT: 0 = fp32 row-major + 2*resid;  1 = bf16 head-major;  2 = fp32 offattn-12
// ---------------------------------------------------------------------------
template <int N, int AT, int WT, int CT>
__global__ __launch_bounds__(256) void mma_gemm(
    const void* __restrict__ Av,
    const float* __restrict__ W1, const float* __restrict__ W2,
    const float* __restrict__ bias1, const float* __restrict__ bias2,
    const float* __restrict__ resid, void* __restrict__ Cv)
{
    constexpr int AST = 136;       // A smem row stride (bf16)
    constexpr int WST = N + 8;
    constexpr int WN = N / 2;
    constexpr int NF = WN / 8;

    extern __shared__ __nv_bfloat16 sm[];
    __nv_bfloat16* As = sm;                  // [128][AST]
    __nv_bfloat16* Ws = sm + 128 * AST;      // [128][WST]

    const int t = threadIdx.x;
    const int rowBase = blockIdx.x * 128;

    // --- load A tile 128x128 -> bf16 smem ---
    if (AT == 0) {
        const float* A = (const float*)Av;
#pragma unroll
        for (int j = 0; j < 16; j++) {
            const int idx = t + j * 256;
            const int row = idx >> 5;
            const int c4  = idx & 31;
            float4 v = *(const float4*)(A + (size_t)(rowBase + row) * EMB + c4 * 4);
            *(__nv_bfloat162*)(As + row * AST + c4 * 4)     = __floats2bfloat162_rn(v.x, v.y);
            *(__nv_bfloat162*)(As + row * AST + c4 * 4 + 2) = __floats2bfloat162_rn(v.z, v.w);
        }
    } else {
        const __nv_bfloat16* A = (const __nv_bfloat16*)Av;
#pragma unroll
        for (int j = 0; j < 8; j++) {
            const int idx = t + j * 256;          // 2048 x 16B
            const int row = idx >> 4;
            const int c8  = idx & 15;
            const int h = c8 >> 1, d = (c8 & 1) * 8;
            const int gr = rowBase + row;
            const int b0 = gr >> 14, q0 = gr & 16383;
            const uint4 v = *(const uint4*)(A + ((size_t)(b0 * 8 + h) * NQ + q0) * 16 + d);
            *(uint4*)(As + row * AST + c8 * 8) = v;
        }
    }
    // --- load W tile 128xN fp32 -> bf16 ---
    constexpr int WF4 = 128 * (N / 4);
    for (int idx = t; idx < WF4; idx += 256) {
        const int row = idx / (N / 4);
        const int cg  = idx % (N / 4);
        float4 v;
        if (WT == 0) {
            v = *(const float4*)(W1 + (size_t)row * N + cg * 4);
        } else {
            const int c = cg * 4;
            if (c < 64) v = *(const float4*)(W1 + (size_t)row * 64 + c);
            else        v = *(const float4*)(W2 + (size_t)row * 32 + (c - 64));
        }
        *(__nv_bfloat162*)(Ws + row * WST + cg * 4)     = __floats2bfloat162_rn(v.x, v.y);
        *(__nv_bfloat162*)(Ws + row * WST + cg * 4 + 2) = __floats2bfloat162_rn(v.z, v.w);
    }
    __syncthreads();

    const int wid = t >> 5, lane = t & 31;
    const int wm = wid & 3, wn = wid >> 2;
    const int m0 = wm * 32;
    const int n0 = wn * WN;

    float acc[2][NF][4];
#pragma unroll
    for (int mf = 0; mf < 2; mf++)
#pragma unroll
        for (int nf = 0; nf < NF; nf++)
#pragma unroll
            for (int i = 0; i < 4; i++) acc[mf][nf][i] = 0.0f;

    const uint32_t asb = smem_u32(As);
    const uint32_t wsb = smem_u32(Ws);
    uint32_t aAddr[2];
#pragma unroll
    for (int mf = 0; mf < 2; mf++)
        aAddr[mf] = asb + ((m0 + mf * 16 + (lane & 15)) * AST + (lane >> 4) * 8) * 2;
    const int kOff = ((lane >> 3) & 1) * 8 + (lane & 7);
    const int cOff = ((lane >> 4) & 1) * 8;
    uint32_t bAddr[NF / 2];
#pragma unroll
    for (int np = 0; np < NF / 2; np++)
        bAddr[np] = wsb + (kOff * WST + n0 + np * 16 + cOff) * 2;

#pragma unroll
    for (int kk = 0; kk < 8; kk++) {
        uint32_t a[2][4];
        ldsm_x4(a[0][0], a[0][1], a[0][2], a[0][3], aAddr[0] + kk * 32);
        ldsm_x4(a[1][0], a[1][1], a[1][2], a[1][3], aAddr[1] + kk * 32);
        uint32_t b[NF][2];
#pragma unroll
        for (int np = 0; np < NF / 2; np++)
            ldsm_x4t(b[2 * np][0], b[2 * np][1], b[2 * np + 1][0], b[2 * np + 1][1],
                     bAddr[np] + kk * 16 * WST * 2);
#pragma unroll
        for (int mf = 0; mf < 2; mf++)
#pragma unroll
            for (int nf = 0; nf < NF; nf++)
                mma_bf16(acc[mf][nf], a[mf], b[nf]);
    }

    // --- epilogue ---
    const int lr = lane >> 2;
    const int lc = (lane & 3) * 2;
#pragma unroll
    for (int mf = 0; mf < 2; mf++)
#pragma unroll
        for (int nf = 0; nf < NF; nf++) {
            const int row = rowBase + m0 + mf * 16 + lr;
            const int col = n0 + nf * 8 + lc;
            float2 bb;
            if (WT == 0) bb = *(const float2*)(bias1 + col);
            else bb = (col < 64) ? *(const float2*)(bias1 + col)
                                 : *(const float2*)(bias2 + col - 64);
            float2 v0 = make_float2(acc[mf][nf][0] + bb.x, acc[mf][nf][1] + bb.y);
            float2 v1 = make_float2(acc[mf][nf][2] + bb.x, acc[mf][nf][3] + bb.y);
            if (CT == 0) {
                float* C = (float*)Cv;
                float2 r0 = *(const float2*)(resid + (size_t)row * EMB + col);
                float2 r1 = *(const float2*)(resid + (size_t)(row + 8) * EMB + col);
                v0.x += 2.0f * r0.x; v0.y += 2.0f * r0.y;
                v1.x += 2.0f * r1.x; v1.y += 2.0f * r1.y;
                *(float2*)(C + (size_t)row * N + col) = v0;
                *(float2*)(C + (size_t)(row + 8) * N + col) = v1;
            } else if (CT == 1) {
                __nv_bfloat16* C = (__nv_bfloat16*)Cv;
                const int h = col >> 4, d = col & 15;
                const int b0 = row >> 14, q0 = row & 16383;
                const size_t base = (size_t)(b0 * 8 + h) * NQ;
                *(__nv_bfloat162*)(C + (base + q0) * 16 + d)     = __floats2bfloat162_rn(v0.x, v0.y);
                *(__nv_bfloat162*)(C + (base + q0 + 8) * 16 + d) = __floats2bfloat162_rn(v1.x, v1.y);
            } else {
                float* C = (float*)Cv;
                int h, jj;
                if (col < 64) { h = col >> 3; jj = col & 7; }
                else          { h = (col - 64) >> 2; jj = 8 + ((col - 64) & 3); }
                const int b0 = row >> 14, q0 = row & 16383;
                const size_t base = (size_t)(b0 * 8 + h) * NQ;
                *(float2*)(C + (base + q0) * 12 + jj)     = v0;
                *(float2*)(C + (base + q0 + 8) * 12 + jj) = v1;
            }
        }
}

// ---------------------------------------------------------------------------
// Tiled gather: block = (b, h, 16x16 query tile). Stages a 24x24 pixel x 16
// bf16 value tile in smem (swizzled: 16B chunk j of pixel px at slot
// j ^ ((px>>2)&1)), softmax + 16-corner bilinear in fp32, writes bf16.
// Global fallback for corners outside the halo keeps correctness.
// ---------------------------------------------------------------------------
__global__ __launch_bounds__(256) void gather_kernel()
{
    __shared__ uint32_t sv[24 * 24 * 8];   // 18,432 B (16 bf16 per pixel)

    const int blk  = blockIdx.x;
    const int tile = blk & 63;
    const int h    = (blk >> 6) & 7;
    const int b    = blk >> 9;
    const int tx0  = (tile & 7) * 16, ty0 = (tile >> 3) * 16;
    const int xlo  = tx0 - 4, ylo = ty0 - 4;
    const int t    = threadIdx.x;

    const __nv_bfloat16* vsrc = g_value + (size_t)(b * 8 + h) * NQ * 16;

    // --- fill smem tile: 1152 16B chunks ---
#pragma unroll
    for (int ii = 0; ii < 5; ii++) {
        const int i = t + ii * 256;
        if (i < 1152) {
            const int pix = i >> 1, j = i & 1;
            const int py = pix / 24, px = pix - py * 24;
            const int gy = ylo + py, gx = xlo + px;
            uint4 v = make_uint4(0u, 0u, 0u, 0u);
            if ((unsigned)gy < 128u && (unsigned)gx < 128u)
                v = *(const uint4*)(vsrc + (size_t)(gy * BEV + gx) * 16 + j * 8);
            const int slot = j ^ ((px >> 2) & 1);
            *(uint4*)(sv + pix * 8 + slot * 4) = v;
        }
    }

    // --- per-thread parameters (coalesced 48B/thread) ---
    const int x = tx0 + (t & 15), y = ty0 + (t >> 4);
    const int q = y * BEV + x;
    const float* oa = g_offattn + ((size_t)(b * 8 + h) * NQ + q) * 12;
    const float4 A0 = *(const float4*)(oa);
    const float4 A1 = *(const float4*)(oa + 4);
    const float4 A2 = *(const float4*)(oa + 8);
    const float off[8] = {A0.x, A0.y, A0.z, A0.w, A1.x, A1.y, A1.z, A1.w};
    float lg[4] = {A2.x, A2.y, A2.z, A2.w};

    __syncthreads();

    // softmax over points
    const float mx = fmaxf(fmaxf(lg[0], lg[1]), fmaxf(lg[2], lg[3]));
    float aw[4], s = 0.0f;
#pragma unroll
    for (int p = 0; p < 4; p++) { aw[p] = __expf(lg[p] - mx); s += aw[p]; }
    const float inv = 1.0f / s;
#pragma unroll
    for (int p = 0; p < 4; p++) aw[p] *= inv;

    const float scale = 128.0f / 127.0f;
    const float refx = (float)x * scale;
    const float refy = (float)y * scale;

    float2 acc[8];
#pragma unroll
    for (int j = 0; j < 8; j++) acc[j] = make_float2(0.f, 0.f);

#pragma unroll
    for (int p = 0; p < 4; p++) {
        const float px = refx + off[p * 2 + 0] - 0.5f;
        const float py = refy + off[p * 2 + 1] - 0.5f;
        const float x0f = floorf(px), y0f = floorf(py);
        const int x0 = (int)x0f, y0 = (int)y0f;
        const float wx = px - x0f, wy = py - y0f;
        const float w = aw[p];
        const float cws[4] = {w * (1.f - wx) * (1.f - wy), w * wx * (1.f - wy),
                              w * (1.f - wx) * wy,         w * wx * wy};
        const int xs[4] = {x0, x0 + 1, x0, x0 + 1};
        const int ys[4] = {y0, y0, y0 + 1, y0 + 1};
#pragma unroll
        for (int c = 0; c < 4; c++) {
            const int xi = xs[c], yi = ys[c];
            const int sx = xi - xlo, sy = yi - ylo;
            const float cw = cws[c];
            uint4 u0, u1;
            bool have = false;
            if ((unsigned)sx < 24u && (unsigned)sy < 24u) {
                const uint32_t* pp = sv + (sy * 24 + sx) * 8;
                const int sw = (sx >> 2) & 1;
                u0 = *(const uint4*)(pp + (0 ^ sw) * 4);
                u1 = *(const uint4*)(pp + (1 ^ sw) * 4);
                have = true;
            } else if ((unsigned)xi < 128u && (unsigned)yi < 128u) {
                const uint4* cp = (const uint4*)(vsrc + (size_t)(yi * BEV + xi) * 16);
                u0 = cp[0]; u1 = cp[1];
                have = true;
            }
            if (have) {
                const uint32_t uu[8] = {u0.x, u0.y, u0.z, u0.w, u1.x, u1.y, u1.z, u1.w};
#pragma unroll
                for (int j = 0; j < 8; j++) {
                    const float2 cv = __bfloat1622float2(*(const __nv_bfloat162*)&uu[j]);
                    acc[j].x = fmaf(cw, cv.x, acc[j].x);
                    acc[j].y = fmaf(cw, cv.y, acc[j].y);
                }
            }
        }
    }

    __nv_bfloat16* outp = g_sampled + ((size_t)(b * 8 + h) * NQ + q) * 16;
    uint32_t ov[8];
#pragma unroll
    for (int j = 0; j < 8; j++) {
        const __nv_bfloat162 bv = __floats2bfloat162_rn(acc[j].x, acc[j].y);
        ov[j] = *(const uint32_t*)&bv;
    }
    *(uint4*)(outp)     = make_uint4(ov[0], ov[1], ov[2], ov[3]);
    *(uint4*)(outp + 8) = make_uint4(ov[4], ov[5], ov[6], ov[7]);
}

// ---------------------------------------------------------------------------

extern "C" void kernel_launch(void* const* d_in, const int* in_sizes, int n_in,
                              void* d_out, int out_size)
{
    const float* query  = (const float*)d_in[0];
    const float* W_off  = (const float*)d_in[1];
    const float* b_off  = (const float*)d_in[2];
    const float* W_attn = (const float*)d_in[3];
    const float* b_attn = (const float*)d_in[4];
    const float* W_val  = (const float*)d_in[5];
    const float* b_val  = (const float*)d_in[6];
    const float* W_out  = (const float*)d_in[7];
    const float* b_out  = (const float*)d_in[8];
    float* out = (float*)d_out;

    void *gv = nullptr, *goa = nullptr, *gs = nullptr;
    cudaGetSymbolAddress(&gv,  g_value);
    cudaGetSymbolAddress(&goa, g_offattn);
    cudaGetSymbolAddress(&gs,  g_sampled);

    const int smem128 = (128 * 136 + 128 * 136) * 2;   // 69632 B
    const int smem96  = (128 * 136 + 128 * 104) * 2;   // 61440 B
    cudaFuncSetAttribute(mma_gemm<128, 0, 0, 1>, cudaFuncAttributeMaxDynamicSharedMemorySize, smem128);
    cudaFuncSetAttribute(mma_gemm<96, 0, 1, 2>,  cudaFuncAttributeMaxDynamicSharedMemorySize, smem96);
    cudaFuncSetAttribute(mma_gemm<128, 1, 0, 0>, cudaFuncAttributeMaxDynamicSharedMemorySize, smem128);

    // 1) value projection -> bf16 head-major g_value
    mma_gemm<128, 0, 0, 1><<<M_TOTAL / 128, 256, smem128>>>(
        query, W_val, nullptr, b_val, nullptr, nullptr, gv);

    // 2) offset/attn projection (dual-source W) -> 12-float per (b,h,q)
    mma_gemm<96, 0, 1, 2><<<M_TOTAL / 128, 256, smem96>>>(
        query, W_off, W_attn, b_off, b_attn, nullptr, goa);

    // 3) tiled softmax + bilinear gather (bf16 value/sampled)
    gather_kernel<<<BS * NH * 64, 256>>>();

    // 4) output projection + bias + 2*query residual (bf16 A)
    mma_gemm<128, 1, 0, 0><<<M_TOTAL / 128, 256, smem128>>>(
        gs, W_out, nullptr, b_out, nullptr, query, out);
}

// round 9
// speedup vs baseline: 7.3359x; 1.1572x over previous
#include <cuda_runtime.h>
#include <cuda_bf16.h>
#include <cstdint>

#define BS 4
#define NQ 16384
#define EMB 128
#define NH 8
#define NP 4
#define HD 16
#define BEV 128
#define M_TOTAL (BS * NQ)   // 65536

// Scratch (device globals: allocation-guard safe)
__device__ __nv_bfloat16 g_value[M_TOTAL * EMB];    // head-major: ((b*8+h)*NQ+q)*16+d
__device__ float         g_offattn[M_TOTAL * 96];   // ((b*8+h)*NQ+q)*12 : 8 off + 4 logits
__device__ __nv_bfloat16 g_sampled[M_TOTAL * EMB];  // head-major like g_value

// ---------------------------------------------------------------------------
// helpers
// ---------------------------------------------------------------------------
__device__ __forceinline__ uint32_t smem_u32(const void* p) {
    return (uint32_t)__cvta_generic_to_shared(p);
}
__device__ __forceinline__ void ldsm_x4(uint32_t& r0, uint32_t& r1, uint32_t& r2,
                                        uint32_t& r3, uint32_t addr) {
    asm volatile("ldmatrix.sync.aligned.m8n8.x4.shared.b16 {%0,%1,%2,%3},[%4];\n"
                 : "=r"(r0), "=r"(r1), "=r"(r2), "=r"(r3) : "r"(addr));
}
__device__ __forceinline__ void ldsm_x4t(uint32_t& r0, uint32_t& r1, uint32_t& r2,
                                         uint32_t& r3, uint32_t addr) {
    asm volatile("ldmatrix.sync.aligned.m8n8.x4.trans.shared.b16 {%0,%1,%2,%3},[%4];\n"
                 : "=r"(r0), "=r"(r1), "=r"(r2), "=r"(r3) : "r"(addr));
}
__device__ __forceinline__ void mma_bf16(float* d, const uint32_t* a,
                                         const uint32_t* b) {
    asm volatile(
        "mma.sync.aligned.m16n8k16.row.col.f32.bf16.bf16.f32 "
        "{%0,%1,%2,%3},{%4,%5,%6,%7},{%8,%9},{%0,%1,%2,%3};\n"
        : "+f"(d[0]), "+f"(d[1]), "+f"(d[2]), "+f"(d[3])
        : "r"(a[0]), "r"(a[1]), "r"(a[2]), "r"(a[3]), "r"(b[0]), "r"(b[1]));
}
__device__ __forceinline__ void cp_async16(uint32_t saddr, const void* g) {
    asm volatile("cp.async.ca.shared.global [%0], [%1], 16;\n" :: "r"(saddr), "l"(g));
}
__device__ __forceinline__ void cp_async_wait_all() {
    asm volatile("cp.async.commit_group;\ncp.async.wait_group 0;\n" ::: "memory");
}

#define AST 136   // A smem row stride (bf16)

// ---------------------------------------------------------------------------
// Fused projection kernel: 64-row tile per CTA.
//   1) value = q @ W_val + b_val          -> g_value (bf16 head-major)
//   2) offattn = q @ [W_off|W_attn] + b   -> g_offattn (12 fp32 per (b,h,q))
// Warp grid 4m x 2n (8 warps, 256 thr). A tile loaded once.
// ---------------------------------------------------------------------------
__global__ __launch_bounds__(256) void proj_kernel(
    const float* __restrict__ query,
    const float* __restrict__ W_val,  const float* __restrict__ b_val,
    const float* __restrict__ W_off,  const float* __restrict__ b_off,
    const float* __restrict__ W_attn, const float* __restrict__ b_attn)
{
    __shared__ __nv_bfloat16 As[64 * AST];
    __shared__ __nv_bfloat16 Ws[128 * AST];

    const int t = threadIdx.x;
    const int rowBase = blockIdx.x * 64;

    // --- A tile: 64x128 fp32 -> bf16 ---
#pragma unroll
    for (int j = 0; j < 8; j++) {
        const int idx = t + j * 256;
        const int row = idx >> 5, c4 = idx & 31;
        float4 v = *(const float4*)(query + (size_t)(rowBase + row) * EMB + c4 * 4);
        *(__nv_bfloat162*)(As + row * AST + c4 * 4)     = __floats2bfloat162_rn(v.x, v.y);
        *(__nv_bfloat162*)(As + row * AST + c4 * 4 + 2) = __floats2bfloat162_rn(v.z, v.w);
    }
    // --- W_val tile: 128x128 ---
#pragma unroll
    for (int j = 0; j < 16; j++) {
        const int idx = t + j * 256;
        const int row = idx >> 5, c4 = idx & 31;
        float4 v = *(const float4*)(W_val + (size_t)row * 128 + c4 * 4);
        *(__nv_bfloat162*)(Ws + row * AST + c4 * 4)     = __floats2bfloat162_rn(v.x, v.y);
        *(__nv_bfloat162*)(Ws + row * AST + c4 * 4 + 2) = __floats2bfloat162_rn(v.z, v.w);
    }
    __syncthreads();

    const int wid = t >> 5, lane = t & 31;
    const int wm = wid & 3, wn = wid >> 2;
    const int m0 = wm * 16;
    const uint32_t asb = smem_u32(As);
    const uint32_t wsb = smem_u32(Ws);
    const uint32_t aAddr = asb + ((m0 + (lane & 15)) * AST + (lane >> 4) * 8) * 2;
    const int kOff = ((lane >> 3) & 1) * 8 + (lane & 7);
    const int cOff = ((lane >> 4) & 1) * 8;
    const int lr = lane >> 2, lc = (lane & 3) * 2;

    // ===== part 1: value (N=128, warp n-tile 64, NF=8) =====
    {
        const int n0 = wn * 64;
        float acc[8][4];
#pragma unroll
        for (int nf = 0; nf < 8; nf++)
#pragma unroll
            for (int i = 0; i < 4; i++) acc[nf][i] = 0.0f;
        uint32_t bAddr[4];
#pragma unroll
        for (int np = 0; np < 4; np++)
            bAddr[np] = wsb + (kOff * AST + n0 + np * 16 + cOff) * 2;

#pragma unroll
        for (int kk = 0; kk < 8; kk++) {
            uint32_t a[4];
            ldsm_x4(a[0], a[1], a[2], a[3], aAddr + kk * 32);
            uint32_t b[8][2];
#pragma unroll
            for (int np = 0; np < 4; np++)
                ldsm_x4t(b[2 * np][0], b[2 * np][1], b[2 * np + 1][0], b[2 * np + 1][1],
                         bAddr[np] + kk * 16 * AST * 2);
#pragma unroll
            for (int nf = 0; nf < 8; nf++) mma_bf16(acc[nf], a, b[nf]);
        }

        const int row = rowBase + m0 + lr;
        const int b0 = row >> 14, q0 = row & 16383;
#pragma unroll
        for (int nf = 0; nf < 8; nf++) {
            const int col = n0 + nf * 8 + lc;
            const float2 bb = *(const float2*)(b_val + col);
            const int h = col >> 4, d = col & 15;
            const size_t base = (size_t)(b0 * 8 + h) * NQ;
            *(__nv_bfloat162*)(g_value + (base + q0) * 16 + d) =
                __floats2bfloat162_rn(acc[nf][0] + bb.x, acc[nf][1] + bb.y);
            *(__nv_bfloat162*)(g_value + (base + q0 + 8) * 16 + d) =
                __floats2bfloat162_rn(acc[nf][2] + bb.x, acc[nf][3] + bb.y);
        }
    }
    __syncthreads();

    // ===== part 2: offattn (N=96, WST=104, warp n-tile 48, NF=6) =====
    constexpr int WST = 104;
    for (int idx = t; idx < 128 * 24; idx += 256) {
        const int row = idx / 24, cg = idx % 24;
        const int c = cg * 4;
        float4 v = (c < 64) ? *(const float4*)(W_off + (size_t)row * 64 + c)
                            : *(const float4*)(W_attn + (size_t)row * 32 + (c - 64));
        *(__nv_bfloat162*)(Ws + row * WST + c)     = __floats2bfloat162_rn(v.x, v.y);
        *(__nv_bfloat162*)(Ws + row * WST + c + 2) = __floats2bfloat162_rn(v.z, v.w);
    }
    __syncthreads();

    {
        const int n0 = wn * 48;
        float acc[6][4];
#pragma unroll
        for (int nf = 0; nf < 6; nf++)
#pragma unroll
            for (int i = 0; i < 4; i++) acc[nf][i] = 0.0f;
        uint32_t bAddr[3];
#pragma unroll
        for (int np = 0; np < 3; np++)
            bAddr[np] = wsb + (kOff * WST + n0 + np * 16 + cOff) * 2;

#pragma unroll
        for (int kk = 0; kk < 8; kk++) {
            uint32_t a[4];
            ldsm_x4(a[0], a[1], a[2], a[3], aAddr + kk * 32);
            uint32_t b[6][2];
#pragma unroll
            for (int np = 0; np < 3; np++)
                ldsm_x4t(b[2 * np][0], b[2 * np][1], b[2 * np + 1][0], b[2 * np + 1][1],
                         bAddr[np] + kk * 16 * WST * 2);
#pragma unroll
            for (int nf = 0; nf < 6; nf++) mma_bf16(acc[nf], a, b[nf]);
        }

        const int row = rowBase + m0 + lr;
        const int b0 = row >> 14, q0 = row & 16383;
#pragma unroll
        for (int nf = 0; nf < 6; nf++) {
            const int col = n0 + nf * 8 + lc;
            const float2 bb = (col < 64) ? *(const float2*)(b_off + col)
                                         : *(const float2*)(b_attn + col - 64);
            int h, jj;
            if (col < 64) { h = col >> 3; jj = col & 7; }
            else          { h = (col - 64) >> 2; jj = 8 + ((col - 64) & 3); }
            const size_t base = (size_t)(b0 * 8 + h) * NQ;
            *(float2*)(g_offattn + (base + q0) * 12 + jj) =
                make_float2(acc[nf][0] + bb.x, acc[nf][1] + bb.y);
            *(float2*)(g_offattn + (base + q0 + 8) * 12 + jj) =
                make_float2(acc[nf][2] + bb.x, acc[nf][3] + bb.y);
        }
    }
}

// ---------------------------------------------------------------------------
// Output GEMM: out[64 x 128] = sampled(bf16 head-major) @ W_out + b + 2*query
// 64-row tile, warp grid 4m x 2n; A tile filled via cp.async.
// ---------------------------------------------------------------------------
__global__ __launch_bounds__(256) void out_gemm(
    const float* __restrict__ W, const float* __restrict__ bias,
    const float* __restrict__ query, float* __restrict__ C)
{
    __shared__ __nv_bfloat16 As[64 * AST];
    __shared__ __nv_bfloat16 Ws[128 * AST];

    const int t = threadIdx.x;
    const int rowBase = blockIdx.x * 64;
    const uint32_t asb = smem_u32(As);

    // --- A tile: 64 rows x 16 chunks of 16B via cp.async ---
#pragma unroll
    for (int j = 0; j < 4; j++) {
        const int idx = t + j * 256;
        const int row = idx >> 4, c8 = idx & 15;
        const int h = c8 >> 1, d = (c8 & 1) * 8;
        const int gr = rowBase + row;
        const int b0 = gr >> 14, q0 = gr & 16383;
        cp_async16(asb + (row * AST + c8 * 8) * 2,
                   g_sampled + ((size_t)(b0 * 8 + h) * NQ + q0) * 16 + d);
    }
    // --- W tile: 128x128 fp32 -> bf16 ---
#pragma unroll
    for (int j = 0; j < 16; j++) {
        const int idx = t + j * 256;
        const int row = idx >> 5, c4 = idx & 31;
        float4 v = *(const float4*)(W + (size_t)row * 128 + c4 * 4);
        *(__nv_bfloat162*)(Ws + row * AST + c4 * 4)     = __floats2bfloat162_rn(v.x, v.y);
        *(__nv_bfloat162*)(Ws + row * AST + c4 * 4 + 2) = __floats2bfloat162_rn(v.z, v.w);
    }
    cp_async_wait_all();
    __syncthreads();

    const int wid = t >> 5, lane = t & 31;
    const int wm = wid & 3, wn = wid >> 2;
    const int m0 = wm * 16;
    const int n0 = wn * 64;
    const uint32_t wsb = smem_u32(Ws);
    const uint32_t aAddr = asb + ((m0 + (lane & 15)) * AST + (lane >> 4) * 8) * 2;
    const int kOff = ((lane >> 3) & 1) * 8 + (lane & 7);
    const int cOff = ((lane >> 4) & 1) * 8;

    float acc[8][4];
#pragma unroll
    for (int nf = 0; nf < 8; nf++)
#pragma unroll
        for (int i = 0; i < 4; i++) acc[nf][i] = 0.0f;
    uint32_t bAddr[4];
#pragma unroll
    for (int np = 0; np < 4; np++)
        bAddr[np] = wsb + (kOff * AST + n0 + np * 16 + cOff) * 2;

#pragma unroll
    for (int kk = 0; kk < 8; kk++) {
        uint32_t a[4];
        ldsm_x4(a[0], a[1], a[2], a[3], aAddr + kk * 32);
        uint32_t b[8][2];
#pragma unroll
        for (int np = 0; np < 4; np++)
            ldsm_x4t(b[2 * np][0], b[2 * np][1], b[2 * np + 1][0], b[2 * np + 1][1],
                     bAddr[np] + kk * 16 * AST * 2);
#pragma unroll
        for (int nf = 0; nf < 8; nf++) mma_bf16(acc[nf], a, b[nf]);
    }

    const int lr = lane >> 2, lc = (lane & 3) * 2;
    const int row = rowBase + m0 + lr;
#pragma unroll
    for (int nf = 0; nf < 8; nf++) {
        const int col = n0 + nf * 8 + lc;
        const float2 bb = *(const float2*)(bias + col);
        const float2 r0 = *(const float2*)(query + (size_t)row * EMB + col);
        const float2 r1 = *(const float2*)(query + (size_t)(row + 8) * EMB + col);
        *(float2*)(C + (size_t)row * EMB + col) =
            make_float2(acc[nf][0] + bb.x + 2.0f * r0.x, acc[nf][1] + bb.y + 2.0f * r0.y);
        *(float2*)(C + (size_t)(row + 8) * EMB + col) =
            make_float2(acc[nf][2] + bb.x + 2.0f * r1.x, acc[nf][3] + bb.y + 2.0f * r1.y);
    }
}

// ---------------------------------------------------------------------------
// Tiled gather: block = (b, h, 16x16 query tile). 24x24 pixel x 16 bf16 tile
// in smem (chunk j of pixel px at slot j ^ ((px>>2)&1)); softmax + bilinear
// in fp32; global fallback outside halo.
// ---------------------------------------------------------------------------
__global__ __launch_bounds__(256) void gather_kernel()
{
    __shared__ uint32_t sv[24 * 24 * 8];   // 18,432 B

    const int blk  = blockIdx.x;
    const int tile = blk & 63;
    const int h    = (blk >> 6) & 7;
    const int b    = blk >> 9;
    const int tx0  = (tile & 7) * 16, ty0 = (tile >> 3) * 16;
    const int xlo  = tx0 - 4, ylo = ty0 - 4;
    const int t    = threadIdx.x;

    const __nv_bfloat16* vsrc = g_value + (size_t)(b * 8 + h) * NQ * 16;

#pragma unroll
    for (int ii = 0; ii < 5; ii++) {
        const int i = t + ii * 256;
        if (i < 1152) {
            const int pix = i >> 1, j = i & 1;
            const int py = pix / 24, px = pix - py * 24;
            const int gy = ylo + py, gx = xlo + px;
            uint4 v = make_uint4(0u, 0u, 0u, 0u);
            if ((unsigned)gy < 128u && (unsigned)gx < 128u)
                v = *(const uint4*)(vsrc + (size_t)(gy * BEV + gx) * 16 + j * 8);
            const int slot = j ^ ((px >> 2) & 1);
            *(uint4*)(sv + pix * 8 + slot * 4) = v;
        }
    }

    const int x = tx0 + (t & 15), y = ty0 + (t >> 4);
    const int q = y * BEV + x;
    const float* oa = g_offattn + ((size_t)(b * 8 + h) * NQ + q) * 12;
    const float4 A0 = *(const float4*)(oa);
    const float4 A1 = *(const float4*)(oa + 4);
    const float4 A2 = *(const float4*)(oa + 8);
    const float off[8] = {A0.x, A0.y, A0.z, A0.w, A1.x, A1.y, A1.z, A1.w};
    float lg[4] = {A2.x, A2.y, A2.z, A2.w};

    __syncthreads();

    const float mx = fmaxf(fmaxf(lg[0], lg[1]), fmaxf(lg[2], lg[3]));
    float aw[4], s = 0.0f;
#pragma unroll
    for (int p = 0; p < 4; p++) { aw[p] = __expf(lg[p] - mx); s += aw[p]; }
    const float inv = 1.0f / s;
#pragma unroll
    for (int p = 0; p < 4; p++) aw[p] *= inv;

    const float scale = 128.0f / 127.0f;
    const float refx = (float)x * scale;
    const float refy = (float)y * scale;

    float2 acc[8];
#pragma unroll
    for (int j = 0; j < 8; j++) acc[j] = make_float2(0.f, 0.f);

#pragma unroll
    for (int p = 0; p < 4; p++) {
        const float px = refx + off[p * 2 + 0] - 0.5f;
        const float py = refy + off[p * 2 + 1] - 0.5f;
        const float x0f = floorf(px), y0f = floorf(py);
        const int x0 = (int)x0f, y0 = (int)y0f;
        const float wx = px - x0f, wy = py - y0f;
        const float w = aw[p];
        const float cws[4] = {w * (1.f - wx) * (1.f - wy), w * wx * (1.f - wy),
                              w * (1.f - wx) * wy,         w * wx * wy};
        const int xs[4] = {x0, x0 + 1, x0, x0 + 1};
        const int ys[4] = {y0, y0, y0 + 1, y0 + 1};
#pragma unroll
        for (int c = 0; c < 4; c++) {
            const int xi = xs[c], yi = ys[c];
            const int sx = xi - xlo, sy = yi - ylo;
            const float cw = cws[c];
            uint4 u0, u1;
            bool have = false;
            if ((unsigned)sx < 24u && (unsigned)sy < 24u) {
                const uint32_t* pp = sv + (sy * 24 + sx) * 8;
                const int sw = (sx >> 2) & 1;
                u0 = *(const uint4*)(pp + (0 ^ sw) * 4);
                u1 = *(const uint4*)(pp + (1 ^ sw) * 4);
                have = true;
            } else if ((unsigned)xi < 128u && (unsigned)yi < 128u) {
                const uint4* cp = (const uint4*)(vsrc + (size_t)(yi * BEV + xi) * 16);
                u0 = cp[0]; u1 = cp[1];
                have = true;
            }
            if (have) {
                const uint32_t uu[8] = {u0.x, u0.y, u0.z, u0.w, u1.x, u1.y, u1.z, u1.w};
#pragma unroll
                for (int j = 0; j < 8; j++) {
                    const float2 cv = __bfloat1622float2(*(const __nv_bfloat162*)&uu[j]);
                    acc[j].x = fmaf(cw, cv.x, acc[j].x);
                    acc[j].y = fmaf(cw, cv.y, acc[j].y);
                }
            }
        }
    }

    __nv_bfloat16* outp = g_sampled + ((size_t)(b * 8 + h) * NQ + q) * 16;
    uint32_t ov[8];
#pragma unroll
    for (int j = 0; j < 8; j++) {
        const __nv_bfloat162 bv = __floats2bfloat162_rn(acc[j].x, acc[j].y);
        ov[j] = *(const uint32_t*)&bv;
    }
    *(uint4*)(outp)     = make_uint4(ov[0], ov[1], ov[2], ov[3]);
    *(uint4*)(outp + 8) = make_uint4(ov[4], ov[5], ov[6], ov[7]);
}

// ---------------------------------------------------------------------------

extern "C" void kernel_launch(void* const* d_in, const int* in_sizes, int n_in,
                              void* d_out, int out_size)
{
    const float* query  = (const float*)d_in[0];
    const float* W_off  = (const float*)d_in[1];
    const float* b_off  = (const float*)d_in[2];
    const float* W_attn = (const float*)d_in[3];
    const float* b_attn = (const float*)d_in[4];
    const float* W_val  = (const float*)d_in[5];
    const float* b_val  = (const float*)d_in[6];
    const float* W_out  = (const float*)d_in[7];
    const float* b_out  = (const float*)d_in[8];
    float* out = (float*)d_out;

    // 1) fused value + offset/attn projections (64-row tiles)
    proj_kernel<<<M_TOTAL / 64, 256>>>(query, W_val, b_val, W_off, b_off,
                                       W_attn, b_attn);

    // 2) tiled softmax + bilinear gather
    gather_kernel<<<BS * NH * 64, 256>>>();

    // 3) output projection + bias + 2*query residual
    out_gemm<<<M_TOTAL / 64, 256>>>(W_out, b_out, query, out);
}

// round 10
// speedup vs baseline: 8.2853x; 1.1294x over previous
#include <cuda_runtime.h>
#include <cuda_bf16.h>
#include <cstdint>

#define BS 4
#define NQ 16384
#define EMB 128
#define NH 8
#define NP 4
#define HD 16
#define BEV 128
#define M_TOTAL (BS * NQ)   // 65536

// Scratch (device globals: allocation-guard safe)
__device__ __nv_bfloat16 g_value[M_TOTAL * EMB];    // head-major: ((b*8+h)*NQ+q)*16+d
__device__ float         g_offattn[M_TOTAL * 96];   // ((b*8+h)*NQ+q)*12 : 8 off + 4 logits
__device__ __nv_bfloat16 g_sampled[M_TOTAL * EMB];  // head-major like g_value
__device__ __nv_bfloat16 g_Wval16[128 * 128];
__device__ __nv_bfloat16 g_Wout16[128 * 128];
__device__ __nv_bfloat16 g_Wcat16[128 * 96];        // [W_off | W_attn]

// ---------------------------------------------------------------------------
// helpers
// ---------------------------------------------------------------------------
__device__ __forceinline__ uint32_t smem_u32(const void* p) {
    return (uint32_t)__cvta_generic_to_shared(p);
}
__device__ __forceinline__ void ldsm_x4(uint32_t& r0, uint32_t& r1, uint32_t& r2,
                                        uint32_t& r3, uint32_t addr) {
    asm volatile("ldmatrix.sync.aligned.m8n8.x4.shared.b16 {%0,%1,%2,%3},[%4];\n"
                 : "=r"(r0), "=r"(r1), "=r"(r2), "=r"(r3) : "r"(addr));
}
__device__ __forceinline__ void ldsm_x4t(uint32_t& r0, uint32_t& r1, uint32_t& r2,
                                         uint32_t& r3, uint32_t addr) {
    asm volatile("ldmatrix.sync.aligned.m8n8.x4.trans.shared.b16 {%0,%1,%2,%3},[%4];\n"
                 : "=r"(r0), "=r"(r1), "=r"(r2), "=r"(r3) : "r"(addr));
}
__device__ __forceinline__ void mma_bf16(float* d, const uint32_t* a,
                                         const uint32_t* b) {
    asm volatile(
        "mma.sync.aligned.m16n8k16.row.col.f32.bf16.bf16.f32 "
        "{%0,%1,%2,%3},{%4,%5,%6,%7},{%8,%9},{%0,%1,%2,%3};\n"
        : "+f"(d[0]), "+f"(d[1]), "+f"(d[2]), "+f"(d[3])
        : "r"(a[0]), "r"(a[1]), "r"(a[2]), "r"(a[3]), "r"(b[0]), "r"(b[1]));
}
__device__ __forceinline__ void cp_async16(uint32_t saddr, const void* g) {
    asm volatile("cp.async.ca.shared.global [%0], [%1], 16;\n" :: "r"(saddr), "l"(g));
}
__device__ __forceinline__ void cp_commit() {
    asm volatile("cp.async.commit_group;\n" ::: "memory");
}
__device__ __forceinline__ void cp_wait_all() {
    asm volatile("cp.async.wait_group 0;\n" ::: "memory");
}

#define AST 136   // A/Wval smem row stride (bf16)

// ---------------------------------------------------------------------------
// One-shot weight conversion fp32 -> bf16 (+ pack W_off|W_attn)
// ---------------------------------------------------------------------------
__global__ __launch_bounds__(256) void conv_kernel(
    const float* __restrict__ W_val, const float* __restrict__ W_out,
    const float* __restrict__ W_off, const float* __restrict__ W_attn)
{
    const int i = blockIdx.x * 256 + threadIdx.x;   // 176 blocks: 45056 elems
    if (i < 16384) {
        g_Wval16[i] = __float2bfloat16(W_val[i]);
        g_Wout16[i] = __float2bfloat16(W_out[i]);
    } else {
        const int j = i - 16384;
        if (j < 12288) {
            const int k = j / 96, c = j % 96;
            const float v = (c < 64) ? W_off[k * 64 + c] : W_attn[k * 32 + (c - 64)];
            g_Wcat16[j] = __float2bfloat16(v);
        }
    }
}

// ---------------------------------------------------------------------------
// Fused projection kernel: 64-row tile per CTA.
//   1) value = q @ W_val + b_val          -> g_value (bf16 head-major)
//   2) offattn = q @ [W_off|W_attn] + b   -> g_offattn (12 fp32 per (b,h,q))
// Weight tiles filled via cp.async from bf16 globals; A converted in regs.
// ---------------------------------------------------------------------------
__global__ __launch_bounds__(256) void proj_kernel(
    const float* __restrict__ query,
    const float* __restrict__ b_val,
    const float* __restrict__ b_off, const float* __restrict__ b_attn)
{
    __shared__ __nv_bfloat16 As[64 * AST];
    __shared__ __nv_bfloat16 Ws[128 * AST];

    const int t = threadIdx.x;
    const int rowBase = blockIdx.x * 64;
    const uint32_t asb = smem_u32(As);
    const uint32_t wsb = smem_u32(Ws);

    // --- W_val tile via cp.async (2048 x 16B) ---
#pragma unroll
    for (int j = 0; j < 8; j++) {
        const int idx = t + j * 256;
        const int row = idx >> 4, c8 = idx & 15;
        cp_async16(wsb + (row * AST + c8 * 8) * 2, g_Wval16 + row * 128 + c8 * 8);
    }
    cp_commit();

    // --- A tile: 64x128 fp32 -> bf16 (overlaps cp.async) ---
#pragma unroll
    for (int j = 0; j < 8; j++) {
        const int idx = t + j * 256;
        const int row = idx >> 5, c4 = idx & 31;
        float4 v = *(const float4*)(query + (size_t)(rowBase + row) * EMB + c4 * 4);
        *(__nv_bfloat162*)(As + row * AST + c4 * 4)     = __floats2bfloat162_rn(v.x, v.y);
        *(__nv_bfloat162*)(As + row * AST + c4 * 4 + 2) = __floats2bfloat162_rn(v.z, v.w);
    }
    cp_wait_all();
    __syncthreads();

    const int wid = t >> 5, lane = t & 31;
    const int wm = wid & 3, wn = wid >> 2;
    const int m0 = wm * 16;
    const uint32_t aAddr = asb + ((m0 + (lane & 15)) * AST + (lane >> 4) * 8) * 2;
    const int kOff = ((lane >> 3) & 1) * 8 + (lane & 7);
    const int cOff = ((lane >> 4) & 1) * 8;
    const int lr = lane >> 2, lc = (lane & 3) * 2;

    // ===== part 1: value (N=128, warp n-tile 64, NF=8) =====
    float acc[8][4];
    {
        const int n0 = wn * 64;
#pragma unroll
        for (int nf = 0; nf < 8; nf++)
#pragma unroll
            for (int i = 0; i < 4; i++) acc[nf][i] = 0.0f;
        uint32_t bAddr[4];
#pragma unroll
        for (int np = 0; np < 4; np++)
            bAddr[np] = wsb + (kOff * AST + n0 + np * 16 + cOff) * 2;

#pragma unroll
        for (int kk = 0; kk < 8; kk++) {
            uint32_t a[4];
            ldsm_x4(a[0], a[1], a[2], a[3], aAddr + kk * 32);
            uint32_t b[8][2];
#pragma unroll
            for (int np = 0; np < 4; np++)
                ldsm_x4t(b[2 * np][0], b[2 * np][1], b[2 * np + 1][0], b[2 * np + 1][1],
                         bAddr[np] + kk * 16 * AST * 2);
#pragma unroll
            for (int nf = 0; nf < 8; nf++) mma_bf16(acc[nf], a, b[nf]);
        }
    }
    __syncthreads();   // all warps done reading Ws

    // --- issue W_cat cp.async (1536 x 16B), then do part-1 epilogue ---
    constexpr int WST = 104;
#pragma unroll
    for (int j = 0; j < 6; j++) {
        const int idx = t + j * 256;
        const int row = idx / 12, c8 = idx % 12;
        cp_async16(wsb + (row * WST + c8 * 8) * 2, g_Wcat16 + row * 96 + c8 * 8);
    }
    cp_commit();

    {
        const int n0 = wn * 64;
        const int row = rowBase + m0 + lr;
        const int b0 = row >> 14, q0 = row & 16383;
#pragma unroll
        for (int nf = 0; nf < 8; nf++) {
            const int col = n0 + nf * 8 + lc;
            const float2 bb = *(const float2*)(b_val + col);
            const int h = col >> 4, d = col & 15;
            const size_t base = (size_t)(b0 * 8 + h) * NQ;
            *(__nv_bfloat162*)(g_value + (base + q0) * 16 + d) =
                __floats2bfloat162_rn(acc[nf][0] + bb.x, acc[nf][1] + bb.y);
            *(__nv_bfloat162*)(g_value + (base + q0 + 8) * 16 + d) =
                __floats2bfloat162_rn(acc[nf][2] + bb.x, acc[nf][3] + bb.y);
        }
    }
    cp_wait_all();
    __syncthreads();

    // ===== part 2: offattn (N=96, WST=104, warp n-tile 48, NF=6) =====
    {
        const int n0 = wn * 48;
        float ac2[6][4];
#pragma unroll
        for (int nf = 0; nf < 6; nf++)
#pragma unroll
            for (int i = 0; i < 4; i++) ac2[nf][i] = 0.0f;
        uint32_t bAddr[3];
#pragma unroll
        for (int np = 0; np < 3; np++)
            bAddr[np] = wsb + (kOff * WST + n0 + np * 16 + cOff) * 2;

#pragma unroll
        for (int kk = 0; kk < 8; kk++) {
            uint32_t a[4];
            ldsm_x4(a[0], a[1], a[2], a[3], aAddr + kk * 32);
            uint32_t b[6][2];
#pragma unroll
            for (int np = 0; np < 3; np++)
                ldsm_x4t(b[2 * np][0], b[2 * np][1], b[2 * np + 1][0], b[2 * np + 1][1],
                         bAddr[np] + kk * 16 * WST * 2);
#pragma unroll
            for (int nf = 0; nf < 6; nf++) mma_bf16(ac2[nf], a, b[nf]);
        }

        const int row = rowBase + m0 + lr;
        const int b0 = row >> 14, q0 = row & 16383;
#pragma unroll
        for (int nf = 0; nf < 6; nf++) {
            const int col = n0 + nf * 8 + lc;
            const float2 bb = (col < 64) ? *(const float2*)(b_off + col)
                                         : *(const float2*)(b_attn + col - 64);
            int h, jj;
            if (col < 64) { h = col >> 3; jj = col & 7; }
            else          { h = (col - 64) >> 2; jj = 8 + ((col - 64) & 3); }
            const size_t base = (size_t)(b0 * 8 + h) * NQ;
            *(float2*)(g_offattn + (base + q0) * 12 + jj) =
                make_float2(ac2[nf][0] + bb.x, ac2[nf][1] + bb.y);
            *(float2*)(g_offattn + (base + q0 + 8) * 12 + jj) =
                make_float2(ac2[nf][2] + bb.x, ac2[nf][3] + bb.y);
        }
    }
}

// ---------------------------------------------------------------------------
// Output GEMM: out[64 x 128] = sampled(bf16 head-major) @ W_out + b + 2*query
// A and W tiles both filled via cp.async.
// ---------------------------------------------------------------------------
__global__ __launch_bounds__(256) void out_gemm(
    const float* __restrict__ bias,
    const float* __restrict__ query, float* __restrict__ C)
{
    __shared__ __nv_bfloat16 As[64 * AST];
    __shared__ __nv_bfloat16 Ws[128 * AST];

    const int t = threadIdx.x;
    const int rowBase = blockIdx.x * 64;
    const uint32_t asb = smem_u32(As);
    const uint32_t wsb = smem_u32(Ws);

    // --- A tile (1024 x 16B) + W tile (2048 x 16B) via cp.async ---
#pragma unroll
    for (int j = 0; j < 4; j++) {
        const int idx = t + j * 256;
        const int row = idx >> 4, c8 = idx & 15;
        const int h = c8 >> 1, d = (c8 & 1) * 8;
        const int gr = rowBase + row;
        const int b0 = gr >> 14, q0 = gr & 16383;
        cp_async16(asb + (row * AST + c8 * 8) * 2,
                   g_sampled + ((size_t)(b0 * 8 + h) * NQ + q0) * 16 + d);
    }
#pragma unroll
    for (int j = 0; j < 8; j++) {
        const int idx = t + j * 256;
        const int row = idx >> 4, c8 = idx & 15;
        cp_async16(wsb + (row * AST + c8 * 8) * 2, g_Wout16 + row * 128 + c8 * 8);
    }
    cp_commit();
    cp_wait_all();
    __syncthreads();

    const int wid = t >> 5, lane = t & 31;
    const int wm = wid & 3, wn = wid >> 2;
    const int m0 = wm * 16;
    const int n0 = wn * 64;
    const uint32_t aAddr = asb + ((m0 + (lane & 15)) * AST + (lane >> 4) * 8) * 2;
    const int kOff = ((lane >> 3) & 1) * 8 + (lane & 7);
    const int cOff = ((lane >> 4) & 1) * 8;

    float acc[8][4];
#pragma unroll
    for (int nf = 0; nf < 8; nf++)
#pragma unroll
        for (int i = 0; i < 4; i++) acc[nf][i] = 0.0f;
    uint32_t bAddr[4];
#pragma unroll
    for (int np = 0; np < 4; np++)
        bAddr[np] = wsb + (kOff * AST + n0 + np * 16 + cOff) * 2;

#pragma unroll
    for (int kk = 0; kk < 8; kk++) {
        uint32_t a[4];
        ldsm_x4(a[0], a[1], a[2], a[3], aAddr + kk * 32);
        uint32_t b[8][2];
#pragma unroll
        for (int np = 0; np < 4; np++)
            ldsm_x4t(b[2 * np][0], b[2 * np][1], b[2 * np + 1][0], b[2 * np + 1][1],
                     bAddr[np] + kk * 16 * AST * 2);
#pragma unroll
        for (int nf = 0; nf < 8; nf++) mma_bf16(acc[nf], a, b[nf]);
    }

    const int lr = lane >> 2, lc = (lane & 3) * 2;
    const int row = rowBase + m0 + lr;
#pragma unroll
    for (int nf = 0; nf < 8; nf++) {
        const int col = n0 + nf * 8 + lc;
        const float2 bb = *(const float2*)(bias + col);
        const float2 r0 = *(const float2*)(query + (size_t)row * EMB + col);
        const float2 r1 = *(const float2*)(query + (size_t)(row + 8) * EMB + col);
        *(float2*)(C + (size_t)row * EMB + col) =
            make_float2(acc[nf][0] + bb.x + 2.0f * r0.x, acc[nf][1] + bb.y + 2.0f * r0.y);
        *(float2*)(C + (size_t)(row + 8) * EMB + col) =
            make_float2(acc[nf][2] + bb.x + 2.0f * r1.x, acc[nf][3] + bb.y + 2.0f * r1.y);
    }
}

// ---------------------------------------------------------------------------
// Tiled gather: block = (b, h, 16x16 query tile). 24x24 pixel x 16 bf16 tile
// in smem (chunk j of pixel px at slot j ^ ((px>>2)&1)); softmax + bilinear
// in fp32; global fallback outside halo.
// ---------------------------------------------------------------------------
__global__ __launch_bounds__(256) void gather_kernel()
{
    __shared__ uint32_t sv[24 * 24 * 8];   // 18,432 B

    const int blk  = blockIdx.x;
    const int tile = blk & 63;
    const int h    = (blk >> 6) & 7;
    const int b    = blk >> 9;
    const int tx0  = (tile & 7) * 16, ty0 = (tile >> 3) * 16;
    const int xlo  = tx0 - 4, ylo = ty0 - 4;
    const int t    = threadIdx.x;

    const __nv_bfloat16* vsrc = g_value + (size_t)(b * 8 + h) * NQ * 16;

#pragma unroll
    for (int ii = 0; ii < 5; ii++) {
        const int i = t + ii * 256;
        if (i < 1152) {
            const int pix = i >> 1, j = i & 1;
            const int py = pix / 24, px = pix - py * 24;
            const int gy = ylo + py, gx = xlo + px;
            uint4 v = make_uint4(0u, 0u, 0u, 0u);
            if ((unsigned)gy < 128u && (unsigned)gx < 128u)
                v = *(const uint4*)(vsrc + (size_t)(gy * BEV + gx) * 16 + j * 8);
            const int slot = j ^ ((px >> 2) & 1);
            *(uint4*)(sv + pix * 8 + slot * 4) = v;
        }
    }

    const int x = tx0 + (t & 15), y = ty0 + (t >> 4);
    const int q = y * BEV + x;
    const float* oa = g_offattn + ((size_t)(b * 8 + h) * NQ + q) * 12;
    const float4 A0 = *(const float4*)(oa);
    const float4 A1 = *(const float4*)(oa + 4);
    const float4 A2 = *(const float4*)(oa + 8);
    const float off[8] = {A0.x, A0.y, A0.z, A0.w, A1.x, A1.y, A1.z, A1.w};
    float lg[4] = {A2.x, A2.y, A2.z, A2.w};

    __syncthreads();

    const float mx = fmaxf(fmaxf(lg[0], lg[1]), fmaxf(lg[2], lg[3]));
    float aw[4], s = 0.0f;
#pragma unroll
    for (int p = 0; p < 4; p++) { aw[p] = __expf(lg[p] - mx); s += aw[p]; }
    const float inv = 1.0f / s;
#pragma unroll
    for (int p = 0; p < 4; p++) aw[p] *= inv;

    const float scale = 128.0f / 127.0f;
    const float refx = (float)x * scale;
    const float refy = (float)y * scale;

    float2 acc[8];
#pragma unroll
    for (int j = 0; j < 8; j++) acc[j] = make_float2(0.f, 0.f);

#pragma unroll
    for (int p = 0; p < 4; p++) {
        const float px = refx + off[p * 2 + 0] - 0.5f;
        const float py = refy + off[p * 2 + 1] - 0.5f;
        const float x0f = floorf(px), y0f = floorf(py);
        const int x0 = (int)x0f, y0 = (int)y0f;
        const float wx = px - x0f, wy = py - y0f;
        const float w = aw[p];
        const float cws[4] = {w * (1.f - wx) * (1.f - wy), w * wx * (1.f - wy),
                              w * (1.f - wx) * wy,         w * wx * wy};
        const int xs[4] = {x0, x0 + 1, x0, x0 + 1};
        const int ys[4] = {y0, y0, y0 + 1, y0 + 1};
#pragma unroll
        for (int c = 0; c < 4; c++) {
            const int xi = xs[c], yi = ys[c];
            const int sx = xi - xlo, sy = yi - ylo;
            const float cw = cws[c];
            uint4 u0, u1;
            bool have = false;
            if ((unsigned)sx < 24u && (unsigned)sy < 24u) {
                const uint32_t* pp = sv + (sy * 24 + sx) * 8;
                const int sw = (sx >> 2) & 1;
                u0 = *(const uint4*)(pp + (0 ^ sw) * 4);
                u1 = *(const uint4*)(pp + (1 ^ sw) * 4);
                have = true;
            } else if ((unsigned)xi < 128u && (unsigned)yi < 128u) {
                const uint4* cp = (const uint4*)(vsrc + (size_t)(yi * BEV + xi) * 16);
                u0 = cp[0]; u1 = cp[1];
                have = true;
            }
            if (have) {
                const uint32_t uu[8] = {u0.x, u0.y, u0.z, u0.w, u1.x, u1.y, u1.z, u1.w};
#pragma unroll
                for (int j = 0; j < 8; j++) {
                    const float2 cv = __bfloat1622float2(*(const __nv_bfloat162*)&uu[j]);
                    acc[j].x = fmaf(cw, cv.x, acc[j].x);
                    acc[j].y = fmaf(cw, cv.y, acc[j].y);
                }
            }
        }
    }

    __nv_bfloat16* outp = g_sampled + ((size_t)(b * 8 + h) * NQ + q) * 16;
    uint32_t ov[8];
#pragma unroll
    for (int j = 0; j < 8; j++) {
        const __nv_bfloat162 bv = __floats2bfloat162_rn(acc[j].x, acc[j].y);
        ov[j] = *(const uint32_t*)&bv;
    }
    *(uint4*)(outp)     = make_uint4(ov[0], ov[1], ov[2], ov[3]);
    *(uint4*)(outp + 8) = make_uint4(ov[4], ov[5], ov[6], ov[7]);
}

// ---------------------------------------------------------------------------

extern "C" void kernel_launch(void* const* d_in, const int* in_sizes, int n_in,
                              void* d_out, int out_size)
{
    const float* query  = (const float*)d_in[0];
    const float* W_off  = (const float*)d_in[1];
    const float* b_off  = (const float*)d_in[2];
    const float* W_attn = (const float*)d_in[3];
    const float* b_attn = (const float*)d_in[4];
    const float* W_val  = (const float*)d_in[5];
    const float* b_val  = (const float*)d_in[6];
    const float* W_out  = (const float*)d_in[7];
    const float* b_out  = (const float*)d_in[8];
    float* out = (float*)d_out;

    // 0) one-shot weight conversion to bf16
    conv_kernel<<<176, 256>>>(W_val, W_out, W_off, W_attn);

    // 1) fused value + offset/attn projections (64-row tiles)
    proj_kernel<<<M_TOTAL / 64, 256>>>(query, b_val, b_off, b_attn);

    // 2) tiled softmax + bilinear gather
    gather_kernel<<<BS * NH * 64, 256>>>();

    // 3) output projection + bias + 2*query residual
    out_gemm<<<M_TOTAL / 64, 256>>>(b_out, query, out);
}